// round 11
// baseline (speedup 1.0000x reference)
#include <cuda_runtime.h>
#include <math.h>

#define EMBD 256
#define HID  512
#define BATCH 64
#define SEQ  512
#define NG   2048      // 4*HID
#define WROW 768       // EMB+HID
#define NCLS 50257
#define NCTA 128
#define HS_STRIDE 516  // padded floats per h row in smem (129 float4)

// ---------------- scratch (static device globals; no cudaMalloc allowed) ----
__device__ float g_Gx[(size_t)SEQ * NG * BATCH];   // [t][g][b]  (transposed)
__device__ float g_h[2][BATCH * HID];              // [b][k]
__device__ float g_hbt[HID * BATCH];               // final hidden, [k][b]
__device__ volatile unsigned g_arrive[NCTA];
__device__ volatile unsigned g_release;
__device__ unsigned g_epoch;                       // bumped each launch (replay-safe)

// ---------------- flag-tree grid barrier (all 128 CTAs resident) ------------
__device__ __forceinline__ void gbar(int bx, int tid, unsigned gen) {
    __threadfence();
    __syncthreads();
    if (bx == 0) {
        if (tid > 0 && tid < NCTA) {
            while (g_arrive[tid] < gen) { }
        }
        __syncthreads();
        if (tid == 0) { __threadfence(); g_release = gen; }
    } else {
        if (tid == 0) {
            g_arrive[bx] = gen;
            while (g_release < gen) { }
        }
    }
    __syncthreads();
}

// ---------------- packed f32x2 helpers --------------------------------------
__device__ __forceinline__ void fma2(unsigned long long& d,
                                     unsigned long long a,
                                     unsigned long long b) {
    asm("fma.rn.f32x2 %0, %1, %2, %0;" : "+l"(d) : "l"(a), "l"(b));
}
__device__ __forceinline__ unsigned long long pack2(float v) {
    unsigned long long r;
    asm("mov.b64 %0, {%1, %1};" : "=l"(r) : "f"(v));
    return r;
}
__device__ __forceinline__ void add2(unsigned long long& d, unsigned long long a) {
    asm("add.rn.f32x2 %0, %0, %1;" : "+l"(d) : "l"(a));
}
union U2 { float2 f; unsigned long long u; };
union U4 { float4 f; ulonglong2 u; };
__device__ __forceinline__ float usum(unsigned long long v) {
    U2 x; x.u = v; return x.f.x + x.f.y;
}
// fast sigmoid / tanh via MUFU (proven at rel_err 7e-7)
__device__ __forceinline__ float fsig(float x) {
    return __fdividef(1.f, 1.f + __expf(-x));
}
__device__ __forceinline__ float ftanh(float x) {
    return __fdividef(2.f, 1.f + __expf(-2.f * x)) - 1.f;
}

// ============================================================================
// Kernel 1: Gx = emb[x] . WxT + bias, output TRANSPOSED as [t][g][b].
//   128x128 tile, BK=16, 8x8/thread, f32x2 accumulators paired along j.
//   __launch_bounds__(256,2) forces <=128 regs so 2 CTAs/SM stay resident.
// ============================================================================
__global__ __launch_bounds__(256, 2) void gx_kernel(
    const int* __restrict__ x, const float* __restrict__ emb,
    const float* __restrict__ W, const float* __restrict__ bias)
{
    __shared__ float As[16][128];
    __shared__ float Bs[16][128];
    __shared__ int   tok[128];

    const int tid = threadIdx.x;
    const int m0 = blockIdx.x * 128;
    const int n0 = blockIdx.y * 128;

    if (tid < 128) {
        int m = m0 + tid;
        tok[tid] = x[(m & 63) * SEQ + (m >> 6)];
    }
    __syncthreads();

    const int lm = tid & 127, lq = tid >> 7;
    const int tx = tid & 15,  ty = tid >> 4;

    unsigned long long acc[8][4];
#pragma unroll
    for (int i = 0; i < 8; i++)
#pragma unroll
        for (int jp = 0; jp < 4; jp++) acc[i][jp] = 0ull;

    float4 ra0, ra1, rb0, rb1;
    {
        const float* arow = emb + (size_t)tok[lm] * EMBD;
        ra0 = *(const float4*)(arow + lq * 4);
        ra1 = *(const float4*)(arow + 8 + lq * 4);
        const float* brow = W + (size_t)(n0 + lm) * WROW;
        rb0 = *(const float4*)(brow + lq * 4);
        rb1 = *(const float4*)(brow + 8 + lq * 4);
    }

    for (int kt = 0; kt < 16; kt++) {
        As[lq * 4 + 0][lm] = ra0.x; As[lq * 4 + 1][lm] = ra0.y;
        As[lq * 4 + 2][lm] = ra0.z; As[lq * 4 + 3][lm] = ra0.w;
        As[8 + lq * 4 + 0][lm] = ra1.x; As[8 + lq * 4 + 1][lm] = ra1.y;
        As[8 + lq * 4 + 2][lm] = ra1.z; As[8 + lq * 4 + 3][lm] = ra1.w;
        Bs[lq * 4 + 0][lm] = rb0.x; Bs[lq * 4 + 1][lm] = rb0.y;
        Bs[lq * 4 + 2][lm] = rb0.z; Bs[lq * 4 + 3][lm] = rb0.w;
        Bs[8 + lq * 4 + 0][lm] = rb1.x; Bs[8 + lq * 4 + 1][lm] = rb1.y;
        Bs[8 + lq * 4 + 2][lm] = rb1.z; Bs[8 + lq * 4 + 3][lm] = rb1.w;
        __syncthreads();

        if (kt < 15) {
            int k0 = (kt + 1) * 16;
            const float* arow = emb + (size_t)tok[lm] * EMBD + k0;
            ra0 = *(const float4*)(arow + lq * 4);
            ra1 = *(const float4*)(arow + 8 + lq * 4);
            const float* brow = W + (size_t)(n0 + lm) * WROW + k0;
            rb0 = *(const float4*)(brow + lq * 4);
            rb1 = *(const float4*)(brow + 8 + lq * 4);
        }

#pragma unroll
        for (int k = 0; k < 16; k++) {
            float4 aL = *(const float4*)&As[k][ty * 4];
            float4 aH = *(const float4*)&As[k][64 + ty * 4];
            U4 bL, bH;
            bL.f = *(const float4*)&Bs[k][tx * 4];
            bH.f = *(const float4*)&Bs[k][64 + tx * 4];
            float av[8] = {aL.x, aL.y, aL.z, aL.w, aH.x, aH.y, aH.z, aH.w};
#pragma unroll
            for (int i = 0; i < 8; i++) {
                unsigned long long aa = pack2(av[i]);
                fma2(acc[i][0], aa, bL.u.x);
                fma2(acc[i][1], aa, bL.u.y);
                fma2(acc[i][2], aa, bH.u.x);
                fma2(acc[i][3], aa, bH.u.y);
            }
        }
        __syncthreads();
    }

    // unpack + bias
    float accf[8][8];
    {
        float4 biL = *(const float4*)(bias + n0 + tx * 4);
        float4 biH = *(const float4*)(bias + n0 + 64 + tx * 4);
        float bl[8] = {biL.x, biL.y, biL.z, biL.w, biH.x, biH.y, biH.z, biH.w};
#pragma unroll
        for (int i = 0; i < 8; i++)
#pragma unroll
            for (int jp = 0; jp < 4; jp++) {
                U2 u; u.u = acc[i][jp];
                accf[i][2 * jp]     = u.f.x + bl[2 * jp];
                accf[i][2 * jp + 1] = u.f.y + bl[2 * jp + 1];
            }
    }

    // transposed store: 8 stages of 16 columns through As (16x128 floats)
    float* T = &As[0][0];
    for (int s = 0; s < 8; s++) {
        __syncthreads();
        int txg = s & 3;
        int jbase = (s < 4) ? 0 : 4;
        if ((tx >> 2) == txg) {
#pragma unroll
            for (int q = 0; q < 4; q++) {
                int cl = (tx & 3) * 4 + q;
#pragma unroll
                for (int r = 0; r < 8; r++) {
                    int m_loc = (r >> 2) * 64 + ty * 4 + (r & 3);
                    T[cl * 128 + m_loc] = accf[r][jbase + q];
                }
            }
        }
        __syncthreads();
#pragma unroll
        for (int w = 0; w < 2; w++) {
            int v = tid + w * 256;
            int row = v >> 4;
            int within = v & 15;
            int cl = row >> 1, tl = row & 1;
            float4 val = *(float4*)&T[cl * 128 + tl * 64 + within * 4];
            int t = (m0 >> 6) + tl;
            int gcol = n0 + s * 16 + cl;
            *(float4*)&g_Gx[((size_t)t * NG + gcol) * BATCH + within * 4] = val;
        }
    }
}

// ============================================================================
// Kernel 2: persistent LSTM recurrence. 128 CTAs x 512 threads.
//   Compute decomposition (as round 9): warp = (jp = warp&1, ko = warp>>1),
//   thread covers 2 j and 2 b over a 16-f4 k-slice.
//   NEW: restage split k<256 (all warps, then sync) / k>=256 (late warps
//   ko>=4, named barrier) so chunk1 L2 traffic overlaps early-warp compute.
//   NEW: partials from ALL warps -> red[ko][j'*4+g][b]; finalize spread over
//   all 16 warps (lanes 0-15), one (j,b) pair per thread.
// ============================================================================
__global__ __launch_bounds__(512, 1) void lstm_kernel(const float* __restrict__ W)
{
    extern __shared__ float smem[];
    float* hs = smem;                                  // 64 x 516
    float* ws = smem + BATCH * HS_STRIDE;              // 16 x 512
    unsigned long long* red =
        (unsigned long long*)(smem + BATCH * HS_STRIDE + 16 * HID); // 8 x 1024

    const int tid  = threadIdx.x;
    const int bx   = blockIdx.x;
    const int l    = tid & 31;
    const int warp = tid >> 5;
    const int jp   = warp & 1;             // compute: j = 4bx + 2jp + jj
    const int ko   = warp >> 1;            // compute: k-slice of 16 f4
    const unsigned base = g_epoch;

    // finalize assignment: warp w lanes 0-15 own (j' = w>>2, b = (w&3)*16+l)
    const bool fin = (l < 16);
    const int fj   = warp >> 2;
    const int fb   = (warp & 3) * 16 + l;
    const int j    = bx * 4 + fj;

    for (int i = tid; i < 16 * HID; i += 512) {
        int row = i >> 9;
        int k   = i & 511;
        int jlw = row >> 2, g = row & 3;
        ws[i] = W[(size_t)(g * HID + bx * 4 + jlw) * WROW + EMBD + k];
    }
    for (int i = bx * 512 + tid; i < BATCH * HID; i += NCTA * 512)
        g_h[0][i] = 0.f;

    gbar(bx, tid, base + 1);

    const float4* w00 = (const float4*)(ws + ((jp * 2 + 0) * 4 + 0) * HID) + ko * 16;
    const float4* w01 = (const float4*)(ws + ((jp * 2 + 0) * 4 + 1) * HID) + ko * 16;
    const float4* w02 = (const float4*)(ws + ((jp * 2 + 0) * 4 + 2) * HID) + ko * 16;
    const float4* w03 = (const float4*)(ws + ((jp * 2 + 0) * 4 + 3) * HID) + ko * 16;
    const float4* w10 = (const float4*)(ws + ((jp * 2 + 1) * 4 + 0) * HID) + ko * 16;
    const float4* w11 = (const float4*)(ws + ((jp * 2 + 1) * 4 + 1) * HID) + ko * 16;
    const float4* w12 = (const float4*)(ws + ((jp * 2 + 1) * 4 + 2) * HID) + ko * 16;
    const float4* w13 = (const float4*)(ws + ((jp * 2 + 1) * 4 + 3) * HID) + ko * 16;
    const float4* hp0 = (const float4*)(hs + l * HS_STRIDE) + ko * 16;
    const float4* hp1 = (const float4*)(hs + (l + 32) * HS_STRIDE) + ko * 16;

    float C = 0.f, hv = 0.f;
    int cur = 0;

    for (int t = 0; t < SEQ; t++) {
        // finalize-thread gate-bias prefetch (latency hidden under restage)
        float gf, gi, go, gc;
        if (fin) {
            const float* gxt = g_Gx + (size_t)t * NG * BATCH;
            gf = __ldcg(gxt + (size_t)(0 * HID + j) * BATCH + fb);
            gi = __ldcg(gxt + (size_t)(1 * HID + j) * BATCH + fb);
            go = __ldcg(gxt + (size_t)(2 * HID + j) * BATCH + fb);
            gc = __ldcg(gxt + (size_t)(3 * HID + j) * BATCH + fb);
        }

        const float4* src = (const float4*)g_h[cur];   // rows of 128 f4
        float4* dst = (float4*)hs;                     // rows of 129 f4

        // chunk0 (k < 256): 4096 f4 over all 512 threads
        {
            float4 rr[8];
#pragma unroll
            for (int i = 0; i < 8; i++) {
                int e = tid + (i << 9);
                rr[i] = __ldcg(src + (e >> 6) * 128 + (e & 63));
            }
#pragma unroll
            for (int i = 0; i < 8; i++) {
                int e = tid + (i << 9);
                dst[(e >> 6) * 129 + (e & 63)] = rr[i];
            }
        }
        __syncthreads();           // chunk0 visible; early warps go compute

        if (ko >= 4) {
            // chunk1 (k >= 256): 4096 f4 over late 256 threads, 2 batches
            int tid2 = tid - 256;
#pragma unroll
            for (int h = 0; h < 2; h++) {
                float4 rr[8];
#pragma unroll
                for (int i = 0; i < 8; i++) {
                    int e = tid2 + ((h * 8 + i) << 8);
                    rr[i] = __ldcg(src + (e >> 6) * 128 + 64 + (e & 63));
                }
#pragma unroll
                for (int i = 0; i < 8; i++) {
                    int e = tid2 + ((h * 8 + i) << 8);
                    dst[(e >> 6) * 129 + 64 + (e & 63)] = rr[i];
                }
            }
            asm volatile("bar.sync 1, 256;" ::: "memory");
        }

        unsigned long long a0[8], a1[8];   // [jj*4+g] for b0=l, b1=l+32
#pragma unroll
        for (int i = 0; i < 8; i++) { a0[i] = 0ull; a1[i] = 0ull; }

#pragma unroll
        for (int it = 0; it < 16; it++) {
            U4 ha, hb;
            ha.f = hp0[it]; hb.f = hp1[it];
            U4 w;
            w.f = w00[it];
            fma2(a0[0], ha.u.x, w.u.x); fma2(a0[0], ha.u.y, w.u.y);
            fma2(a1[0], hb.u.x, w.u.x); fma2(a1[0], hb.u.y, w.u.y);
            w.f = w01[it];
            fma2(a0[1], ha.u.x, w.u.x); fma2(a0[1], ha.u.y, w.u.y);
            fma2(a1[1], hb.u.x, w.u.x); fma2(a1[1], hb.u.y, w.u.y);
            w.f = w02[it];
            fma2(a0[2], ha.u.x, w.u.x); fma2(a0[2], ha.u.y, w.u.y);
            fma2(a1[2], hb.u.x, w.u.x); fma2(a1[2], hb.u.y, w.u.y);
            w.f = w03[it];
            fma2(a0[3], ha.u.x, w.u.x); fma2(a0[3], ha.u.y, w.u.y);
            fma2(a1[3], hb.u.x, w.u.x); fma2(a1[3], hb.u.y, w.u.y);
            w.f = w10[it];
            fma2(a0[4], ha.u.x, w.u.x); fma2(a0[4], ha.u.y, w.u.y);
            fma2(a1[4], hb.u.x, w.u.x); fma2(a1[4], hb.u.y, w.u.y);
            w.f = w11[it];
            fma2(a0[5], ha.u.x, w.u.x); fma2(a0[5], ha.u.y, w.u.y);
            fma2(a1[5], hb.u.x, w.u.x); fma2(a1[5], hb.u.y, w.u.y);
            w.f = w12[it];
            fma2(a0[6], ha.u.x, w.u.x); fma2(a0[6], ha.u.y, w.u.y);
            fma2(a1[6], hb.u.x, w.u.x); fma2(a1[6], hb.u.y, w.u.y);
            w.f = w13[it];
            fma2(a0[7], ha.u.x, w.u.x); fma2(a0[7], ha.u.y, w.u.y);
            fma2(a1[7], hb.u.x, w.u.x); fma2(a1[7], hb.u.y, w.u.y);
        }

        // ALL warps store partials: red[ko*1024 + (j'*4+g)*64 + b]
        {
            unsigned long long* r = red + ko * 1024;
#pragma unroll
            for (int i = 0; i < 8; i++) {
                int jj = i >> 2, g = i & 3;
                int rowoff = ((jp * 2 + jj) * 4 + g) * 64;
                r[rowoff + l]      = a0[i];
                r[rowoff + l + 32] = a1[i];
            }
        }
        __syncthreads();

        if (fin) {
            float ag[4];
#pragma unroll
            for (int g = 0; g < 4; g++) {
                const unsigned long long* r = red + (fj * 4 + g) * 64 + fb;
                unsigned long long s = r[0];
#pragma unroll
                for (int k2 = 1; k2 < 8; k2++) add2(s, r[k2 * 1024]);
                ag[g] = usum(s);
            }
            float F = fsig(ag[0] + gf);
            float I = fsig(ag[1] + gi);
            float O = fsig(ag[2] + go);
            C = F * C + I * ftanh(ag[3] + gc);
            hv = O * ftanh(C);
            g_h[cur ^ 1][fb * HID + j] = hv;
        }

        gbar(bx, tid, base + 2 + t);
        cur ^= 1;
    }

    if (fin) g_hbt[(size_t)j * BATCH + fb] = hv;   // [k][b] for fc
    if (bx == 0 && tid == 0) g_epoch = base + SEQ + 8;
}

// ============================================================================
// Kernel 3: out[b][n] = h[b] . fc_weight[n] + fc_bias[n]
//   h staged in smem as [k][b] padded rows; f32x2 over batch pairs.
// ============================================================================
__global__ __launch_bounds__(256, 1) void fc_kernel(
    const float* __restrict__ fcw, const float* __restrict__ fcb,
    float* __restrict__ out)
{
    extern __shared__ float hb2[];   // 512 rows x 68 floats
    const int tid = threadIdx.x;
    for (int i = tid; i < HID * 16; i += 256) {
        int k = i >> 4, q = i & 15;
        ((float4*)(hb2 + k * 68))[q] = ((const float4*)g_hbt)[i];
    }
    __syncthreads();

    const int warp = tid >> 5, lane = tid & 31;
    const int wglobal = blockIdx.x * 8 + warp;
    const int nw = gridDim.x * 8;

    for (int n = wglobal; n < NCLS; n += nw) {
        unsigned long long acc[32];
#pragma unroll
        for (int i = 0; i < 32; i++) acc[i] = 0ull;
        const float* wrow = fcw + (size_t)n * HID;
#pragma unroll
        for (int kk = 0; kk < 16; kk++) {
            int k = kk * 32 + lane;
            unsigned long long ww = pack2(wrow[k]);
            const float4* hrow = (const float4*)(hb2 + k * 68);
#pragma unroll
            for (int q = 0; q < 16; q++) {
                U4 hh; hh.f = hrow[q];
                fma2(acc[2 * q],     ww, hh.u.x);
                fma2(acc[2 * q + 1], ww, hh.u.y);
            }
        }
        float bias = fcb[n];
#pragma unroll
        for (int p = 0; p < 32; p++) {
            unsigned long long v = acc[p];
            add2(v, __shfl_xor_sync(0xffffffffu, v, 16));
            add2(v, __shfl_xor_sync(0xffffffffu, v, 8));
            add2(v, __shfl_xor_sync(0xffffffffu, v, 4));
            add2(v, __shfl_xor_sync(0xffffffffu, v, 2));
            add2(v, __shfl_xor_sync(0xffffffffu, v, 1));
            if (lane == 0) {
                U2 u; u.u = v;
                out[(size_t)(2 * p) * NCLS + n]     = u.f.x + bias;
                out[(size_t)(2 * p + 1) * NCLS + n] = u.f.y + bias;
            }
        }
    }
}

// ============================================================================
extern "C" void kernel_launch(void* const* d_in, const int* in_sizes, int n_in,
                              void* d_out, int out_size)
{
    const int*   x   = (const int*)d_in[0];
    const float* emb = (const float*)d_in[1];
    const float* W   = (const float*)d_in[2];
    const float* Wb  = (const float*)d_in[3];
    const float* fcw = (const float*)d_in[4];
    const float* fcb = (const float*)d_in[5];
    float* out = (float*)d_out;

    // hs 132096 B + ws 32768 B + red 8*1024*8 = 65536 B -> 230400 B
    static const size_t lstm_smem =
        (size_t)(BATCH * HS_STRIDE + 16 * HID) * 4 + (size_t)8 * 1024 * 8;
    static const size_t fc_smem = (size_t)HID * 68 * 4;      // 139264
    cudaFuncSetAttribute(lstm_kernel, cudaFuncAttributeMaxDynamicSharedMemorySize,
                         (int)lstm_smem);
    cudaFuncSetAttribute(fc_kernel, cudaFuncAttributeMaxDynamicSharedMemorySize,
                         (int)fc_smem);

    dim3 g1(SEQ * BATCH / 128, NG / 128);
    gx_kernel<<<g1, 256>>>(x, emb, W, Wb);

    lstm_kernel<<<NCTA, 512, lstm_smem>>>(W);

    fc_kernel<<<148, 256, fc_smem>>>(fcw, fcb, out);
}

// round 12
// speedup vs baseline: 1.0274x; 1.0274x over previous
#include <cuda_runtime.h>
#include <math.h>

#define EMBD 256
#define HID  512
#define BATCH 64
#define SEQ  512
#define NG   2048      // 4*HID
#define WROW 768       // EMB+HID
#define NCLS 50257
#define NCTA 128
#define HS_STRIDE 516  // padded floats per h row in smem (129 float4)

// ---------------- scratch (static device globals; no cudaMalloc allowed) ----
__device__ float g_Gx[(size_t)SEQ * NG * BATCH];   // [t][g][b]  (transposed)
__device__ float g_h[2][BATCH * HID];              // [b][k]
__device__ float g_hbt[HID * BATCH];               // final hidden, [k][b]
__device__ volatile unsigned g_arrive[NCTA * 32];  // padded: flag at bx*32
__device__ unsigned g_epoch;                       // bumped each launch (replay-safe)

// ---------------- one-hop all-to-all grid barrier ---------------------------
__device__ __forceinline__ void gbar(int bx, int tid, unsigned gen) {
    __threadfence();
    __syncthreads();
    if (tid == 0) g_arrive[bx * 32] = gen;
    if (tid < NCTA) {
        while (g_arrive[tid * 32] < gen) { }
    }
    __syncthreads();
}

// ---------------- packed f32x2 helpers --------------------------------------
__device__ __forceinline__ void fma2(unsigned long long& d,
                                     unsigned long long a,
                                     unsigned long long b) {
    asm("fma.rn.f32x2 %0, %1, %2, %0;" : "+l"(d) : "l"(a), "l"(b));
}
__device__ __forceinline__ unsigned long long pack2(float v) {
    unsigned long long r;
    asm("mov.b64 %0, {%1, %1};" : "=l"(r) : "f"(v));
    return r;
}
__device__ __forceinline__ void add2(unsigned long long& d, unsigned long long a) {
    asm("add.rn.f32x2 %0, %0, %1;" : "+l"(d) : "l"(a));
}
union U2 { float2 f; unsigned long long u; };
union U4 { float4 f; ulonglong2 u; };
__device__ __forceinline__ float usum(unsigned long long v) {
    U2 x; x.u = v; return x.f.x + x.f.y;
}
// fast sigmoid / tanh via MUFU (proven at rel_err 7e-7)
__device__ __forceinline__ float fsig(float x) {
    return __fdividef(1.f, 1.f + __expf(-x));
}
__device__ __forceinline__ float ftanh(float x) {
    return __fdividef(2.f, 1.f + __expf(-2.f * x)) - 1.f;
}

// ============================================================================
// Kernel 1: Gx = emb[x] . WxT + bias, output TRANSPOSED as [t][g][b].
//   128x128 tile, BK=16, 8x8/thread, scalar FFMA (proven 726us body - frozen).
// ============================================================================
__global__ __launch_bounds__(256) void gx_kernel(
    const int* __restrict__ x, const float* __restrict__ emb,
    const float* __restrict__ W, const float* __restrict__ bias)
{
    __shared__ float As[16][128];
    __shared__ float Bs[16][128];
    __shared__ int   tok[128];

    const int tid = threadIdx.x;
    const int m0 = blockIdx.x * 128;
    const int n0 = blockIdx.y * 128;

    if (tid < 128) {
        int m = m0 + tid;
        tok[tid] = x[(m & 63) * SEQ + (m >> 6)];
    }
    __syncthreads();

    const int lm = tid & 127, lq = tid >> 7;
    const int tx = tid & 15,  ty = tid >> 4;

    float acc[8][8];
#pragma unroll
    for (int i = 0; i < 8; i++)
#pragma unroll
        for (int jj = 0; jj < 8; jj++) acc[i][jj] = 0.f;

    float4 ra0, ra1, rb0, rb1;
    {
        const float* arow = emb + (size_t)tok[lm] * EMBD;
        ra0 = *(const float4*)(arow + lq * 4);
        ra1 = *(const float4*)(arow + 8 + lq * 4);
        const float* brow = W + (size_t)(n0 + lm) * WROW;
        rb0 = *(const float4*)(brow + lq * 4);
        rb1 = *(const float4*)(brow + 8 + lq * 4);
    }

    for (int kt = 0; kt < 16; kt++) {
        As[lq * 4 + 0][lm] = ra0.x; As[lq * 4 + 1][lm] = ra0.y;
        As[lq * 4 + 2][lm] = ra0.z; As[lq * 4 + 3][lm] = ra0.w;
        As[8 + lq * 4 + 0][lm] = ra1.x; As[8 + lq * 4 + 1][lm] = ra1.y;
        As[8 + lq * 4 + 2][lm] = ra1.z; As[8 + lq * 4 + 3][lm] = ra1.w;
        Bs[lq * 4 + 0][lm] = rb0.x; Bs[lq * 4 + 1][lm] = rb0.y;
        Bs[lq * 4 + 2][lm] = rb0.z; Bs[lq * 4 + 3][lm] = rb0.w;
        Bs[8 + lq * 4 + 0][lm] = rb1.x; Bs[8 + lq * 4 + 1][lm] = rb1.y;
        Bs[8 + lq * 4 + 2][lm] = rb1.z; Bs[8 + lq * 4 + 3][lm] = rb1.w;
        __syncthreads();

        if (kt < 15) {
            int k0 = (kt + 1) * 16;
            const float* arow = emb + (size_t)tok[lm] * EMBD + k0;
            ra0 = *(const float4*)(arow + lq * 4);
            ra1 = *(const float4*)(arow + 8 + lq * 4);
            const float* brow = W + (size_t)(n0 + lm) * WROW + k0;
            rb0 = *(const float4*)(brow + lq * 4);
            rb1 = *(const float4*)(brow + 8 + lq * 4);
        }

#pragma unroll
        for (int k = 0; k < 16; k++) {
            float4 aL = *(const float4*)&As[k][ty * 4];
            float4 aH = *(const float4*)&As[k][64 + ty * 4];
            float4 bL = *(const float4*)&Bs[k][tx * 4];
            float4 bH = *(const float4*)&Bs[k][64 + tx * 4];
            float av[8] = {aL.x, aL.y, aL.z, aL.w, aH.x, aH.y, aH.z, aH.w};
            float bv[8] = {bL.x, bL.y, bL.z, bL.w, bH.x, bH.y, bH.z, bH.w};
#pragma unroll
            for (int i = 0; i < 8; i++)
#pragma unroll
                for (int jj = 0; jj < 8; jj++)
                    acc[i][jj] = fmaf(av[i], bv[jj], acc[i][jj]);
        }
        __syncthreads();
    }

    {
        float4 biL = *(const float4*)(bias + n0 + tx * 4);
        float4 biH = *(const float4*)(bias + n0 + 64 + tx * 4);
        float bl[8] = {biL.x, biL.y, biL.z, biL.w, biH.x, biH.y, biH.z, biH.w};
#pragma unroll
        for (int r = 0; r < 8; r++)
#pragma unroll
            for (int cc = 0; cc < 8; cc++) acc[r][cc] += bl[cc];
    }

    // transposed store: 8 stages of 16 columns through As (16x128 floats)
    float* T = &As[0][0];
    for (int s = 0; s < 8; s++) {
        __syncthreads();
        int txg = s & 3;
        int jbase = (s < 4) ? 0 : 4;
        if ((tx >> 2) == txg) {
#pragma unroll
            for (int q = 0; q < 4; q++) {
                int cl = (tx & 3) * 4 + q;
#pragma unroll
                for (int r = 0; r < 8; r++) {
                    int m_loc = (r >> 2) * 64 + ty * 4 + (r & 3);
                    T[cl * 128 + m_loc] = acc[r][jbase + q];
                }
            }
        }
        __syncthreads();
#pragma unroll
        for (int w = 0; w < 2; w++) {
            int v = tid + w * 256;
            int row = v >> 4;
            int within = v & 15;
            int cl = row >> 1, tl = row & 1;
            float4 val = *(float4*)&T[cl * 128 + tl * 64 + within * 4];
            int t = (m0 >> 6) + tl;
            int gcol = n0 + s * 16 + cl;
            *(float4*)&g_Gx[((size_t)t * NG + gcol) * BATCH + within * 4] = val;
        }
    }
}

// ============================================================================
// Kernel 2: persistent LSTM recurrence. 128 CTAs x 512 threads.
//   Warp = (jp = warp&1, ko = warp>>1). Thread covers 2 j, 2 b, 16-f4 k-slice.
//   NEW: pair-sliced restage — warp restages ONLY its pair's k-slice (jp
//   picks rows 0..31 / 32..63), syncs with its partner warp via a named
//   barrier, and computes immediately. Compute overlaps the chip-wide L2
//   restage drain instead of waiting for it.
//   Parallel finalize over all 16 warps (lanes 0-15), one (j,b) per thread.
// ============================================================================
__global__ __launch_bounds__(512, 1) void lstm_kernel(const float* __restrict__ W)
{
    extern __shared__ float smem[];
    float* hs = smem;                                  // 64 x 516
    float* ws = smem + BATCH * HS_STRIDE;              // 16 x 512
    unsigned long long* red =
        (unsigned long long*)(smem + BATCH * HS_STRIDE + 16 * HID); // 8 x 1024

    const int tid  = threadIdx.x;
    const int bx   = blockIdx.x;
    const int l    = tid & 31;
    const int warp = tid >> 5;
    const int jp   = warp & 1;             // j-pair: j = 4bx + 2jp + jj
    const int ko   = warp >> 1;            // 0..7, k-slice of 16 f4
    const unsigned base = g_epoch;

    // finalize assignment: warp w lanes 0-15 own (j' = w>>2, b = (w&3)*16+l)
    const bool fin = (l < 16);
    const int fj   = warp >> 2;
    const int fb   = (warp & 3) * 16 + l;
    const int j    = bx * 4 + fj;

    for (int i = tid; i < 16 * HID; i += 512) {
        int row = i >> 9;
        int k   = i & 511;
        int jlw = row >> 2, g = row & 3;
        ws[i] = W[(size_t)(g * HID + bx * 4 + jlw) * WROW + EMBD + k];
    }
    for (int i = bx * 512 + tid; i < BATCH * HID; i += NCTA * 512)
        g_h[0][i] = 0.f;

    gbar(bx, tid, base + 1);

    const float4* w00 = (const float4*)(ws + ((jp * 2 + 0) * 4 + 0) * HID) + ko * 16;
    const float4* w01 = (const float4*)(ws + ((jp * 2 + 0) * 4 + 1) * HID) + ko * 16;
    const float4* w02 = (const float4*)(ws + ((jp * 2 + 0) * 4 + 2) * HID) + ko * 16;
    const float4* w03 = (const float4*)(ws + ((jp * 2 + 0) * 4 + 3) * HID) + ko * 16;
    const float4* w10 = (const float4*)(ws + ((jp * 2 + 1) * 4 + 0) * HID) + ko * 16;
    const float4* w11 = (const float4*)(ws + ((jp * 2 + 1) * 4 + 1) * HID) + ko * 16;
    const float4* w12 = (const float4*)(ws + ((jp * 2 + 1) * 4 + 2) * HID) + ko * 16;
    const float4* w13 = (const float4*)(ws + ((jp * 2 + 1) * 4 + 3) * HID) + ko * 16;
    const float4* hp0 = (const float4*)(hs + l * HS_STRIDE) + ko * 16;
    const float4* hp1 = (const float4*)(hs + (l + 32) * HS_STRIDE) + ko * 16;

    float C = 0.f, hv = 0.f;
    int cur = 0;

    for (int t = 0; t < SEQ; t++) {
        // finalize-thread gate-bias prefetch (latency hidden under restage)
        float gf, gi, go, gc;
        if (fin) {
            const float* gxt = g_Gx + (size_t)t * NG * BATCH;
            gf = __ldcg(gxt + (size_t)(0 * HID + j) * BATCH + fb);
            gi = __ldcg(gxt + (size_t)(1 * HID + j) * BATCH + fb);
            go = __ldcg(gxt + (size_t)(2 * HID + j) * BATCH + fb);
            gc = __ldcg(gxt + (size_t)(3 * HID + j) * BATCH + fb);
        }

        // pair-sliced restage: this warp loads rows [jp*32, jp*32+32) of
        // f4-columns [ko*16, ko*16+16): 512 f4, 16 per lane.
        // e = it*32 + l -> local row e>>4, q = e&15 (two 256B segs / instr).
        {
            const float4* src = (const float4*)g_h[cur];   // rows of 128 f4
            float4* dst = (float4*)hs;                     // rows of 129 f4
            float4 rr[16];
#pragma unroll
            for (int i = 0; i < 16; i++) {
                int e = (i << 5) + l;
                int grow = jp * 32 + (e >> 4);
                rr[i] = __ldcg(src + grow * 128 + ko * 16 + (e & 15));
            }
#pragma unroll
            for (int i = 0; i < 16; i++) {
                int e = (i << 5) + l;
                int grow = jp * 32 + (e >> 4);
                dst[grow * 129 + ko * 16 + (e & 15)] = rr[i];
            }
        }
        // sync only with partner warp (other jp, same ko)
        asm volatile("bar.sync %0, 64;" :: "r"(1 + ko) : "memory");

        unsigned long long a0[8], a1[8];   // [jj*4+g] for b0=l, b1=l+32
#pragma unroll
        for (int i = 0; i < 8; i++) { a0[i] = 0ull; a1[i] = 0ull; }

#pragma unroll
        for (int it = 0; it < 16; it++) {
            U4 ha, hb;
            ha.f = hp0[it]; hb.f = hp1[it];
            U4 w;
            w.f = w00[it];
            fma2(a0[0], ha.u.x, w.u.x); fma2(a0[0], ha.u.y, w.u.y);
            fma2(a1[0], hb.u.x, w.u.x); fma2(a1[0], hb.u.y, w.u.y);
            w.f = w01[it];
            fma2(a0[1], ha.u.x, w.u.x); fma2(a0[1], ha.u.y, w.u.y);
            fma2(a1[1], hb.u.x, w.u.x); fma2(a1[1], hb.u.y, w.u.y);
            w.f = w02[it];
            fma2(a0[2], ha.u.x, w.u.x); fma2(a0[2], ha.u.y, w.u.y);
            fma2(a1[2], hb.u.x, w.u.x); fma2(a1[2], hb.u.y, w.u.y);
            w.f = w03[it];
            fma2(a0[3], ha.u.x, w.u.x); fma2(a0[3], ha.u.y, w.u.y);
            fma2(a1[3], hb.u.x, w.u.x); fma2(a1[3], hb.u.y, w.u.y);
            w.f = w10[it];
            fma2(a0[4], ha.u.x, w.u.x); fma2(a0[4], ha.u.y, w.u.y);
            fma2(a1[4], hb.u.x, w.u.x); fma2(a1[4], hb.u.y, w.u.y);
            w.f = w11[it];
            fma2(a0[5], ha.u.x, w.u.x); fma2(a0[5], ha.u.y, w.u.y);
            fma2(a1[5], hb.u.x, w.u.x); fma2(a1[5], hb.u.y, w.u.y);
            w.f = w12[it];
            fma2(a0[6], ha.u.x, w.u.x); fma2(a0[6], ha.u.y, w.u.y);
            fma2(a1[6], hb.u.x, w.u.x); fma2(a1[6], hb.u.y, w.u.y);
            w.f = w13[it];
            fma2(a0[7], ha.u.x, w.u.x); fma2(a0[7], ha.u.y, w.u.y);
            fma2(a1[7], hb.u.x, w.u.x); fma2(a1[7], hb.u.y, w.u.y);
        }

        // ALL warps store partials: red[ko*1024 + (j'*4+g)*64 + b]
        {
            unsigned long long* r = red + ko * 1024;
#pragma unroll
            for (int i = 0; i < 8; i++) {
                int jj = i >> 2, g = i & 3;
                int rowoff = ((jp * 2 + jj) * 4 + g) * 64;
                r[rowoff + l]      = a0[i];
                r[rowoff + l + 32] = a1[i];
            }
        }
        __syncthreads();

        if (fin) {
            float ag[4];
#pragma unroll
            for (int g = 0; g < 4; g++) {
                const unsigned long long* r = red + (fj * 4 + g) * 64 + fb;
                unsigned long long s = r[0];
#pragma unroll
                for (int k2 = 1; k2 < 8; k2++) add2(s, r[k2 * 1024]);
                ag[g] = usum(s);
            }
            float F = fsig(ag[0] + gf);
            float I = fsig(ag[1] + gi);
            float O = fsig(ag[2] + go);
            C = F * C + I * ftanh(ag[3] + gc);
            hv = O * ftanh(C);
            g_h[cur ^ 1][fb * HID + j] = hv;
        }

        gbar(bx, tid, base + 2 + t);
        cur ^= 1;
    }

    if (fin) g_hbt[(size_t)j * BATCH + fb] = hv;   // [k][b] for fc
    if (bx == 0 && tid == 0) g_epoch = base + SEQ + 8;
}

// ============================================================================
// Kernel 3: out[b][n] = h[b] . fc_weight[n] + fc_bias[n]
//   h staged in smem as [k][b] padded rows; f32x2 over batch pairs.
// ============================================================================
__global__ __launch_bounds__(256, 1) void fc_kernel(
    const float* __restrict__ fcw, const float* __restrict__ fcb,
    float* __restrict__ out)
{
    extern __shared__ float hb2[];   // 512 rows x 68 floats
    const int tid = threadIdx.x;
    for (int i = tid; i < HID * 16; i += 256) {
        int k = i >> 4, q = i & 15;
        ((float4*)(hb2 + k * 68))[q] = ((const float4*)g_hbt)[i];
    }
    __syncthreads();

    const int warp = tid >> 5, lane = tid & 31;
    const int wglobal = blockIdx.x * 8 + warp;
    const int nw = gridDim.x * 8;

    for (int n = wglobal; n < NCLS; n += nw) {
        unsigned long long acc[32];
#pragma unroll
        for (int i = 0; i < 32; i++) acc[i] = 0ull;
        const float* wrow = fcw + (size_t)n * HID;
#pragma unroll
        for (int kk = 0; kk < 16; kk++) {
            int k = kk * 32 + lane;
            unsigned long long ww = pack2(wrow[k]);
            const float4* hrow = (const float4*)(hb2 + k * 68);
#pragma unroll
            for (int q = 0; q < 16; q++) {
                U4 hh; hh.f = hrow[q];
                fma2(acc[2 * q],     ww, hh.u.x);
                fma2(acc[2 * q + 1], ww, hh.u.y);
            }
        }
        float bias = fcb[n];
#pragma unroll
        for (int p = 0; p < 32; p++) {
            unsigned long long v = acc[p];
            add2(v, __shfl_xor_sync(0xffffffffu, v, 16));
            add2(v, __shfl_xor_sync(0xffffffffu, v, 8));
            add2(v, __shfl_xor_sync(0xffffffffu, v, 4));
            add2(v, __shfl_xor_sync(0xffffffffu, v, 2));
            add2(v, __shfl_xor_sync(0xffffffffu, v, 1));
            if (lane == 0) {
                U2 u; u.u = v;
                out[(size_t)(2 * p) * NCLS + n]     = u.f.x + bias;
                out[(size_t)(2 * p + 1) * NCLS + n] = u.f.y + bias;
            }
        }
    }
}

// ============================================================================
extern "C" void kernel_launch(void* const* d_in, const int* in_sizes, int n_in,
                              void* d_out, int out_size)
{
    const int*   x   = (const int*)d_in[0];
    const float* emb = (const float*)d_in[1];
    const float* W   = (const float*)d_in[2];
    const float* Wb  = (const float*)d_in[3];
    const float* fcw = (const float*)d_in[4];
    const float* fcb = (const float*)d_in[5];
    float* out = (float*)d_out;

    // hs 132096 B + ws 32768 B + red 8*1024*8 = 65536 B -> 230400 B
    static const size_t lstm_smem =
        (size_t)(BATCH * HS_STRIDE + 16 * HID) * 4 + (size_t)8 * 1024 * 8;
    static const size_t fc_smem = (size_t)HID * 68 * 4;      // 139264
    cudaFuncSetAttribute(lstm_kernel, cudaFuncAttributeMaxDynamicSharedMemorySize,
                         (int)lstm_smem);
    cudaFuncSetAttribute(fc_kernel, cudaFuncAttributeMaxDynamicSharedMemorySize,
                         (int)fc_smem);

    dim3 g1(SEQ * BATCH / 128, NG / 128);
    gx_kernel<<<g1, 256>>>(x, emb, W, Wb);

    lstm_kernel<<<NCTA, 512, lstm_smem>>>(W);

    fc_kernel<<<148, 256, fc_smem>>>(fcw, fcb, out);
}

// round 13
// speedup vs baseline: 1.0368x; 1.0092x over previous
#include <cuda_runtime.h>
#include <math.h>

#define EMBD 256
#define HID  512
#define BATCH 64
#define SEQ  512
#define NG   2048      // 4*HID
#define WROW 768       // EMB+HID
#define NCLS 50257
#define NCTA 128

// ---------------- scratch (static device globals; no cudaMalloc allowed) ----
__device__ float g_Gx[(size_t)SEQ * NG * BATCH];   // [t][g][b]  (transposed)
// h quad-interleaved: g_h4[buf][kp*32 + bp] = {h[2kp][2bp], h[2kp][2bp+1],
//                                              h[2kp+1][2bp], h[2kp+1][2bp+1]}
__device__ float4 g_h4[2][256 * 32];
__device__ float g_hbt[HID * BATCH];               // final hidden, [k][b]
__device__ volatile unsigned g_arrive[NCTA * 32];  // padded flag at bx*32
__device__ unsigned g_epoch;                       // bumped each launch

// ---------------- one-hop all-to-all grid barrier ---------------------------
__device__ __forceinline__ void gbar(int bx, int tid, unsigned gen) {
    __threadfence();
    __syncthreads();
    if (tid == 0) g_arrive[bx * 32] = gen;
    if (tid < NCTA) {
        while (g_arrive[tid * 32] < gen) { }
    }
    __syncthreads();
}

// ---------------- packed f32x2 helpers --------------------------------------
__device__ __forceinline__ void fma2(unsigned long long& d,
                                     unsigned long long a,
                                     unsigned long long b) {
    asm("fma.rn.f32x2 %0, %1, %2, %0;" : "+l"(d) : "l"(a), "l"(b));
}
__device__ __forceinline__ unsigned long long pack2(float v) {
    unsigned long long r;
    asm("mov.b64 %0, {%1, %1};" : "=l"(r) : "f"(v));
    return r;
}
__device__ __forceinline__ void add2(unsigned long long& d, unsigned long long a) {
    asm("add.rn.f32x2 %0, %0, %1;" : "+l"(d) : "l"(a));
}
union U2 { float2 f; unsigned long long u; };
union U4 { float4 f; ulonglong2 u; };
__device__ __forceinline__ float usum(unsigned long long v) {
    U2 x; x.u = v; return x.f.x + x.f.y;
}
__device__ __forceinline__ float fsig(float x) {
    return __fdividef(1.f, 1.f + __expf(-x));
}
__device__ __forceinline__ float ftanh(float x) {
    return __fdividef(2.f, 1.f + __expf(-2.f * x)) - 1.f;
}

// ============================================================================
// Kernel 1: Gx = emb[x] . WxT + bias, output TRANSPOSED as [t][g][b].
//   (frozen proven body)
// ============================================================================
__global__ __launch_bounds__(256) void gx_kernel(
    const int* __restrict__ x, const float* __restrict__ emb,
    const float* __restrict__ W, const float* __restrict__ bias)
{
    __shared__ float As[16][128];
    __shared__ float Bs[16][128];
    __shared__ int   tok[128];

    const int tid = threadIdx.x;
    const int m0 = blockIdx.x * 128;
    const int n0 = blockIdx.y * 128;

    if (tid < 128) {
        int m = m0 + tid;
        tok[tid] = x[(m & 63) * SEQ + (m >> 6)];
    }
    __syncthreads();

    const int lm = tid & 127, lq = tid >> 7;
    const int tx = tid & 15,  ty = tid >> 4;

    float acc[8][8];
#pragma unroll
    for (int i = 0; i < 8; i++)
#pragma unroll
        for (int jj = 0; jj < 8; jj++) acc[i][jj] = 0.f;

    float4 ra0, ra1, rb0, rb1;
    {
        const float* arow = emb + (size_t)tok[lm] * EMBD;
        ra0 = *(const float4*)(arow + lq * 4);
        ra1 = *(const float4*)(arow + 8 + lq * 4);
        const float* brow = W + (size_t)(n0 + lm) * WROW;
        rb0 = *(const float4*)(brow + lq * 4);
        rb1 = *(const float4*)(brow + 8 + lq * 4);
    }

    for (int kt = 0; kt < 16; kt++) {
        As[lq * 4 + 0][lm] = ra0.x; As[lq * 4 + 1][lm] = ra0.y;
        As[lq * 4 + 2][lm] = ra0.z; As[lq * 4 + 3][lm] = ra0.w;
        As[8 + lq * 4 + 0][lm] = ra1.x; As[8 + lq * 4 + 1][lm] = ra1.y;
        As[8 + lq * 4 + 2][lm] = ra1.z; As[8 + lq * 4 + 3][lm] = ra1.w;
        Bs[lq * 4 + 0][lm] = rb0.x; Bs[lq * 4 + 1][lm] = rb0.y;
        Bs[lq * 4 + 2][lm] = rb0.z; Bs[lq * 4 + 3][lm] = rb0.w;
        Bs[8 + lq * 4 + 0][lm] = rb1.x; Bs[8 + lq * 4 + 1][lm] = rb1.y;
        Bs[8 + lq * 4 + 2][lm] = rb1.z; Bs[8 + lq * 4 + 3][lm] = rb1.w;
        __syncthreads();

        if (kt < 15) {
            int k0 = (kt + 1) * 16;
            const float* arow = emb + (size_t)tok[lm] * EMBD + k0;
            ra0 = *(const float4*)(arow + lq * 4);
            ra1 = *(const float4*)(arow + 8 + lq * 4);
            const float* brow = W + (size_t)(n0 + lm) * WROW + k0;
            rb0 = *(const float4*)(brow + lq * 4);
            rb1 = *(const float4*)(brow + 8 + lq * 4);
        }

#pragma unroll
        for (int k = 0; k < 16; k++) {
            float4 aL = *(const float4*)&As[k][ty * 4];
            float4 aH = *(const float4*)&As[k][64 + ty * 4];
            float4 bL = *(const float4*)&Bs[k][tx * 4];
            float4 bH = *(const float4*)&Bs[k][64 + tx * 4];
            float av[8] = {aL.x, aL.y, aL.z, aL.w, aH.x, aH.y, aH.z, aH.w};
            float bv[8] = {bL.x, bL.y, bL.z, bL.w, bH.x, bH.y, bH.z, bH.w};
#pragma unroll
            for (int i = 0; i < 8; i++)
#pragma unroll
                for (int jj = 0; jj < 8; jj++)
                    acc[i][jj] = fmaf(av[i], bv[jj], acc[i][jj]);
        }
        __syncthreads();
    }

    {
        float4 biL = *(const float4*)(bias + n0 + tx * 4);
        float4 biH = *(const float4*)(bias + n0 + 64 + tx * 4);
        float bl[8] = {biL.x, biL.y, biL.z, biL.w, biH.x, biH.y, biH.z, biH.w};
#pragma unroll
        for (int r = 0; r < 8; r++)
#pragma unroll
            for (int cc = 0; cc < 8; cc++) acc[r][cc] += bl[cc];
    }

    float* T = &As[0][0];
    for (int s = 0; s < 8; s++) {
        __syncthreads();
        int txg = s & 3;
        int jbase = (s < 4) ? 0 : 4;
        if ((tx >> 2) == txg) {
#pragma unroll
            for (int q = 0; q < 4; q++) {
                int cl = (tx & 3) * 4 + q;
#pragma unroll
                for (int r = 0; r < 8; r++) {
                    int m_loc = (r >> 2) * 64 + ty * 4 + (r & 3);
                    T[cl * 128 + m_loc] = acc[r][jbase + q];
                }
            }
        }
        __syncthreads();
#pragma unroll
        for (int w = 0; w < 2; w++) {
            int v = tid + w * 256;
            int row = v >> 4;
            int within = v & 15;
            int cl = row >> 1, tl = row & 1;
            float4 val = *(float4*)&T[cl * 128 + tl * 64 + within * 4];
            int t = (m0 >> 6) + tl;
            int gcol = n0 + s * 16 + cl;
            *(float4*)&g_Gx[((size_t)t * NG + gcol) * BATCH + within * 4] = val;
        }
    }
}

// ============================================================================
// Kernel 2: persistent LSTM recurrence — DIRECT-LDG (no smem h staging).
//   128 CTAs x 512 threads. Warp = ko (0..15): k-slice of 16 kp (32 k).
//   Lane = bp: batches (2bp, 2bp+1). Thread accumulates ALL 16 (j,g) dots
//   as float2-over-b via fma2, fed by one LDG.128 h-quad per kp and 16
//   broadcast LDS.128 dup-weight pairs. 16-way k-reduction in smem red,
//   finalize spread over all 16 warps (lanes 0-15).
// ============================================================================
__global__ __launch_bounds__(512, 1) void lstm_kernel(const float* __restrict__ W)
{
    extern __shared__ float smem[];
    float* ws2f = smem;                                   // dup weights: 16384 f (64KB)
    unsigned long long* red =
        (unsigned long long*)(smem + 16 * HID * 2);       // 16*512 u64 (64KB)

    const int tid  = threadIdx.x;
    const int bx   = blockIdx.x;
    const int l    = tid & 31;             // bp: batches 2l, 2l+1
    const int warp = tid >> 5;
    const int ko   = warp;                 // k-slice: kp in [ko*16, ko*16+16)
    const unsigned base = g_epoch;

    // finalize assignment: warp w lanes 0-15 own (fj = w>>2, fb = (w&3)*16+l)
    const bool fin = (l < 16);
    const int fj   = warp >> 2;
    const int fb   = (warp & 3) * 16 + l;
    const int j    = bx * 4 + fj;

    // build duplicated weight table: ws2f[(jg*256 + kp)*4 + half*2 + {0,1}] = w
    // jg = jl*4 + g
    for (int i = tid; i < 16 * HID; i += 512) {
        int jg = i >> 9;                   // 0..15
        int k  = i & 511;
        int jl = jg >> 2, g = jg & 3;
        float w = W[(size_t)(g * HID + bx * 4 + jl) * WROW + EMBD + k];
        int kp = k >> 1, half = k & 1;
        ws2f[(jg * 256 + kp) * 4 + half * 2 + 0] = w;
        ws2f[(jg * 256 + kp) * 4 + half * 2 + 1] = w;
    }
    // zero h buffer 0 (quad layout)
    for (int i = bx * 512 + tid; i < 256 * 32; i += NCTA * 512)
        g_h4[0][i] = make_float4(0.f, 0.f, 0.f, 0.f);

    gbar(bx, tid, base + 1);

    const float4* wbase = (const float4*)ws2f + ko * 16;  // + jg*256 + it

    float C = 0.f, hv = 0.f;
    int cur = 0;

    for (int t = 0; t < SEQ; t++) {
        // finalize-thread gate-bias prefetch (latency hidden under compute)
        float gf, gi, go, gc;
        if (fin) {
            const float* gxt = g_Gx + (size_t)t * NG * BATCH;
            gf = __ldcg(gxt + (size_t)(0 * HID + j) * BATCH + fb);
            gi = __ldcg(gxt + (size_t)(1 * HID + j) * BATCH + fb);
            go = __ldcg(gxt + (size_t)(2 * HID + j) * BATCH + fb);
            gc = __ldcg(gxt + (size_t)(3 * HID + j) * BATCH + fb);
        }

        unsigned long long acc[16];
#pragma unroll
        for (int i = 0; i < 16; i++) acc[i] = 0ull;

        // direct-LDG compute: 16 kp iterations; h straight from L2.
        const float4* hq = g_h4[cur] + ko * 16 * 32;
#pragma unroll 8
        for (int it = 0; it < 16; it++) {
            U4 hh; hh.f = __ldcg(hq + it * 32 + l);
#pragma unroll
            for (int jg = 0; jg < 16; jg++) {
                U4 w; w.f = wbase[jg * 256 + it];
                fma2(acc[jg], hh.u.x, w.u.x);
                fma2(acc[jg], hh.u.y, w.u.y);
            }
        }

        // store partials: red[ko*512 + jg*32 + bp]
        {
            unsigned long long* r = red + ko * 512 + l;
#pragma unroll
            for (int jg = 0; jg < 16; jg++) r[jg * 32] = acc[jg];
        }
        __syncthreads();

        if (fin) {
            const int bp = fb >> 1, hi = fb & 1;
            const float* redf = (const float*)red;
            float ag[4];
#pragma unroll
            for (int g = 0; g < 4; g++) {
                int idx = ((fj * 4 + g) * 32 + bp) * 2 + hi;
                float s = redf[idx];
#pragma unroll
                for (int ks = 1; ks < 16; ks++) s += redf[ks * 1024 + idx];
                ag[g] = s;
            }
            float F = fsig(ag[0] + gf);
            float I = fsig(ag[1] + gi);
            float O = fsig(ag[2] + go);
            C = F * C + I * ftanh(ag[3] + gc);
            hv = O * ftanh(C);
            // scatter into quad layout of the next buffer
            float* gh = (float*)g_h4[cur ^ 1];
            gh[((j >> 1) * 32 + (fb >> 1)) * 4 + (j & 1) * 2 + (fb & 1)] = hv;
        }

        gbar(bx, tid, base + 2 + t);
        cur ^= 1;
    }

    if (fin) g_hbt[(size_t)j * BATCH + fb] = hv;   // [k][b] for fc
    if (bx == 0 && tid == 0) g_epoch = base + SEQ + 8;
}

// ============================================================================
// Kernel 3: out[b][n] = h[b] . fc_weight[n] + fc_bias[n]   (frozen)
// ============================================================================
__global__ __launch_bounds__(256, 1) void fc_kernel(
    const float* __restrict__ fcw, const float* __restrict__ fcb,
    float* __restrict__ out)
{
    extern __shared__ float hb2[];   // 512 rows x 68 floats
    const int tid = threadIdx.x;
    for (int i = tid; i < HID * 16; i += 256) {
        int k = i >> 4, q = i & 15;
        ((float4*)(hb2 + k * 68))[q] = ((const float4*)g_hbt)[i];
    }
    __syncthreads();

    const int warp = tid >> 5, lane = tid & 31;
    const int wglobal = blockIdx.x * 8 + warp;
    const int nw = gridDim.x * 8;

    for (int n = wglobal; n < NCLS; n += nw) {
        unsigned long long acc[32];
#pragma unroll
        for (int i = 0; i < 32; i++) acc[i] = 0ull;
        const float* wrow = fcw + (size_t)n * HID;
#pragma unroll
        for (int kk = 0; kk < 16; kk++) {
            int k = kk * 32 + lane;
            unsigned long long ww = pack2(wrow[k]);
            const float4* hrow = (const float4*)(hb2 + k * 68);
#pragma unroll
            for (int q = 0; q < 16; q++) {
                U4 hh; hh.f = hrow[q];
                fma2(acc[2 * q],     ww, hh.u.x);
                fma2(acc[2 * q + 1], ww, hh.u.y);
            }
        }
        float bias = fcb[n];
#pragma unroll
        for (int p = 0; p < 32; p++) {
            unsigned long long v = acc[p];
            add2(v, __shfl_xor_sync(0xffffffffu, v, 16));
            add2(v, __shfl_xor_sync(0xffffffffu, v, 8));
            add2(v, __shfl_xor_sync(0xffffffffu, v, 4));
            add2(v, __shfl_xor_sync(0xffffffffu, v, 2));
            add2(v, __shfl_xor_sync(0xffffffffu, v, 1));
            if (lane == 0) {
                U2 u; u.u = v;
                out[(size_t)(2 * p) * NCLS + n]     = u.f.x + bias;
                out[(size_t)(2 * p + 1) * NCLS + n] = u.f.y + bias;
            }
        }
    }
}

// ============================================================================
extern "C" void kernel_launch(void* const* d_in, const int* in_sizes, int n_in,
                              void* d_out, int out_size)
{
    const int*   x   = (const int*)d_in[0];
    const float* emb = (const float*)d_in[1];
    const float* W   = (const float*)d_in[2];
    const float* Wb  = (const float*)d_in[3];
    const float* fcw = (const float*)d_in[4];
    const float* fcb = (const float*)d_in[5];
    float* out = (float*)d_out;

    // ws2 64 KB + red 64 KB = 131072 B
    static const size_t lstm_smem = (size_t)16 * HID * 2 * 4 + (size_t)16 * 512 * 8;
    static const size_t fc_smem = (size_t)HID * 68 * 4;      // 139264
    cudaFuncSetAttribute(lstm_kernel, cudaFuncAttributeMaxDynamicSharedMemorySize,
                         (int)lstm_smem);
    cudaFuncSetAttribute(fc_kernel, cudaFuncAttributeMaxDynamicSharedMemorySize,
                         (int)fc_smem);

    dim3 g1(SEQ * BATCH / 128, NG / 128);
    gx_kernel<<<g1, 256>>>(x, emb, W, Wb);

    lstm_kernel<<<NCTA, 512, lstm_smem>>>(W);

    fc_kernel<<<148, 256, fc_smem>>>(fcw, fcb, out);
}

// round 14
// speedup vs baseline: 1.1384x; 1.0980x over previous
#include <cuda_runtime.h>
#include <math.h>

#define EMBD 256
#define HID  512
#define BATCH 64
#define SEQ  512
#define NG   2048      // 4*HID
#define WROW 768       // EMB+HID
#define NCLS 50257
#define NCTA 128
#define GSIZE 32       // CTAs per group
#define NGROUP 4       // independent batch groups
#define GBATCH 16      // batches per group

// ---------------- scratch (static device globals; no cudaMalloc allowed) ----
__device__ float g_Gx[(size_t)SEQ * NG * BATCH];   // [t][g][b]  (transposed)
// per-group h, quad layout: g_hq[buf][grp][kq*16 + b_loc] = h[b][4kq..4kq+3]
__device__ float4 g_hq[2][NGROUP][128 * 16];
__device__ float g_hbt[HID * BATCH];               // final hidden, [k][b]
__device__ volatile unsigned g_arrive[NCTA * 32];  // padded flag at bx*32
__device__ unsigned g_epoch;                       // bumped each launch

// ---------------- group-scope one-hop barrier (32 CTAs) ----------------------
__device__ __forceinline__ void gbarg(int grp, int tid, unsigned gen) {
    __threadfence();
    __syncthreads();
    if (tid == 0) g_arrive[(grp * GSIZE + (blockIdx.x & 31)) * 32] = gen;
    if (tid < GSIZE) {
        while (g_arrive[(grp * GSIZE + tid) * 32] < gen) { }
    }
    __syncthreads();
}

// ---------------- packed f32x2 helpers --------------------------------------
__device__ __forceinline__ void fma2(unsigned long long& d,
                                     unsigned long long a,
                                     unsigned long long b) {
    asm("fma.rn.f32x2 %0, %1, %2, %0;" : "+l"(d) : "l"(a), "l"(b));
}
__device__ __forceinline__ unsigned long long pack2(float v) {
    unsigned long long r;
    asm("mov.b64 %0, {%1, %1};" : "=l"(r) : "f"(v));
    return r;
}
__device__ __forceinline__ void add2(unsigned long long& d, unsigned long long a) {
    asm("add.rn.f32x2 %0, %0, %1;" : "+l"(d) : "l"(a));
}
union U2 { float2 f; unsigned long long u; };
union U4 { float4 f; ulonglong2 u; };
__device__ __forceinline__ float usum(unsigned long long v) {
    U2 x; x.u = v; return x.f.x + x.f.y;
}
__device__ __forceinline__ float fsig(float x) {
    return __fdividef(1.f, 1.f + __expf(-x));
}
__device__ __forceinline__ float ftanh(float x) {
    return __fdividef(2.f, 1.f + __expf(-2.f * x)) - 1.f;
}

// ============================================================================
// Kernel 1: Gx = emb[x] . WxT + bias, output TRANSPOSED as [t][g][b]. (frozen)
// ============================================================================
__global__ __launch_bounds__(256) void gx_kernel(
    const int* __restrict__ x, const float* __restrict__ emb,
    const float* __restrict__ W, const float* __restrict__ bias)
{
    __shared__ float As[16][128];
    __shared__ float Bs[16][128];
    __shared__ int   tok[128];

    const int tid = threadIdx.x;
    const int m0 = blockIdx.x * 128;
    const int n0 = blockIdx.y * 128;

    if (tid < 128) {
        int m = m0 + tid;
        tok[tid] = x[(m & 63) * SEQ + (m >> 6)];
    }
    __syncthreads();

    const int lm = tid & 127, lq = tid >> 7;
    const int tx = tid & 15,  ty = tid >> 4;

    float acc[8][8];
#pragma unroll
    for (int i = 0; i < 8; i++)
#pragma unroll
        for (int jj = 0; jj < 8; jj++) acc[i][jj] = 0.f;

    float4 ra0, ra1, rb0, rb1;
    {
        const float* arow = emb + (size_t)tok[lm] * EMBD;
        ra0 = *(const float4*)(arow + lq * 4);
        ra1 = *(const float4*)(arow + 8 + lq * 4);
        const float* brow = W + (size_t)(n0 + lm) * WROW;
        rb0 = *(const float4*)(brow + lq * 4);
        rb1 = *(const float4*)(brow + 8 + lq * 4);
    }

    for (int kt = 0; kt < 16; kt++) {
        As[lq * 4 + 0][lm] = ra0.x; As[lq * 4 + 1][lm] = ra0.y;
        As[lq * 4 + 2][lm] = ra0.z; As[lq * 4 + 3][lm] = ra0.w;
        As[8 + lq * 4 + 0][lm] = ra1.x; As[8 + lq * 4 + 1][lm] = ra1.y;
        As[8 + lq * 4 + 2][lm] = ra1.z; As[8 + lq * 4 + 3][lm] = ra1.w;
        Bs[lq * 4 + 0][lm] = rb0.x; Bs[lq * 4 + 1][lm] = rb0.y;
        Bs[lq * 4 + 2][lm] = rb0.z; Bs[lq * 4 + 3][lm] = rb0.w;
        Bs[8 + lq * 4 + 0][lm] = rb1.x; Bs[8 + lq * 4 + 1][lm] = rb1.y;
        Bs[8 + lq * 4 + 2][lm] = rb1.z; Bs[8 + lq * 4 + 3][lm] = rb1.w;
        __syncthreads();

        if (kt < 15) {
            int k0 = (kt + 1) * 16;
            const float* arow = emb + (size_t)tok[lm] * EMBD + k0;
            ra0 = *(const float4*)(arow + lq * 4);
            ra1 = *(const float4*)(arow + 8 + lq * 4);
            const float* brow = W + (size_t)(n0 + lm) * WROW + k0;
            rb0 = *(const float4*)(brow + lq * 4);
            rb1 = *(const float4*)(brow + 8 + lq * 4);
        }

#pragma unroll
        for (int k = 0; k < 16; k++) {
            float4 aL = *(const float4*)&As[k][ty * 4];
            float4 aH = *(const float4*)&As[k][64 + ty * 4];
            float4 bL = *(const float4*)&Bs[k][tx * 4];
            float4 bH = *(const float4*)&Bs[k][64 + tx * 4];
            float av[8] = {aL.x, aL.y, aL.z, aL.w, aH.x, aH.y, aH.z, aH.w};
            float bv[8] = {bL.x, bL.y, bL.z, bL.w, bH.x, bH.y, bH.z, bH.w};
#pragma unroll
            for (int i = 0; i < 8; i++)
#pragma unroll
                for (int jj = 0; jj < 8; jj++)
                    acc[i][jj] = fmaf(av[i], bv[jj], acc[i][jj]);
        }
        __syncthreads();
    }

    {
        float4 biL = *(const float4*)(bias + n0 + tx * 4);
        float4 biH = *(const float4*)(bias + n0 + 64 + tx * 4);
        float bl[8] = {biL.x, biL.y, biL.z, biL.w, biH.x, biH.y, biH.z, biH.w};
#pragma unroll
        for (int r = 0; r < 8; r++)
#pragma unroll
            for (int cc = 0; cc < 8; cc++) acc[r][cc] += bl[cc];
    }

    float* T = &As[0][0];
    for (int s = 0; s < 8; s++) {
        __syncthreads();
        int txg = s & 3;
        int jbase = (s < 4) ? 0 : 4;
        if ((tx >> 2) == txg) {
#pragma unroll
            for (int q = 0; q < 4; q++) {
                int cl = (tx & 3) * 4 + q;
#pragma unroll
                for (int r = 0; r < 8; r++) {
                    int m_loc = (r >> 2) * 64 + ty * 4 + (r & 3);
                    T[cl * 128 + m_loc] = acc[r][jbase + q];
                }
            }
        }
        __syncthreads();
#pragma unroll
        for (int w = 0; w < 2; w++) {
            int v = tid + w * 256;
            int row = v >> 4;
            int within = v & 15;
            int cl = row >> 1, tl = row & 1;
            float4 val = *(float4*)&T[cl * 128 + tl * 64 + within * 4];
            int t = (m0 >> 6) + tl;
            int gcol = n0 + s * 16 + cl;
            *(float4*)&g_Gx[((size_t)t * NG + gcol) * BATCH + within * 4] = val;
        }
    }
}

// ============================================================================
// Kernel 2: persistent LSTM — 4 INDEPENDENT groups of 32 CTAs.
//   Group g owns batches [16g,16g+16); CTA c in group owns j in [16c,16c+16)
//   (64 weight rows, 128KB smem, stationary). No cross-group sync at all.
//   Thread: warp = ko (32-k slice), lane = (jh 0..1, b 0..15). Accs are
//   k-paired f32x2 (plain weights, no duplication). 16-way k-reduction in
//   smem; finalize on tid<256 (one (j,b) each).
// ============================================================================
__global__ __launch_bounds__(512, 1) void lstm_kernel(const float* __restrict__ W)
{
    extern __shared__ float smem[];
    float* ws = smem;                               // 64 x 512 f (128 KB)
    float4* red4 = (float4*)(smem + 64 * HID);      // 4096 f4  (64 KB)

    const int tid  = threadIdx.x;
    const int bx   = blockIdx.x;
    const int grp  = bx >> 5;
    const int c    = bx & 31;
    const int l    = tid & 31;
    const int ko   = tid >> 5;             // warp: k-slice [ko*32, ko*32+32)
    const int b    = l & 15;               // batch within group
    const int jh   = l >> 4;               // j-half (8 j each)
    const unsigned base = g_epoch;

    const bool fin = (tid < 256);
    const int fj = tid >> 4;               // 0..15 (valid when fin)
    const int fb = tid & 15;
    const int jgf = c * 16 + fj;           // global j of finalizer
    const int bgf = grp * GBATCH + fb;     // global batch of finalizer

    // stationary weights: ws[(j_loc*4+gate)*512 + k]
    for (int i = tid; i < 64 * HID; i += 512) {
        int row = i >> 9;                  // j_loc*4+gate
        int k   = i & 511;
        int j_loc = row >> 2, gate = row & 3;
        ws[i] = W[(size_t)(gate * HID + c * 16 + j_loc) * WROW + EMBD + k];
    }
    // zero this group's h buffer 0 (CTA 0 of the group)
    if (c == 0) {
        for (int i = tid; i < 128 * 16; i += 512)
            g_hq[0][grp][i] = make_float4(0.f, 0.f, 0.f, 0.f);
    }

    gbarg(grp, tid, base + 1);

    const float4* ws4 = (const float4*)ws;        // row*128 + kq
    float C = 0.f, hv = 0.f;
    int cur = 0;

    for (int t = 0; t < SEQ; t++) {
        float gf, gi, go, gc;
        if (fin) {
            const float* gxt = g_Gx + (size_t)t * NG * BATCH;
            gf = __ldcg(gxt + (size_t)(0 * HID + jgf) * BATCH + bgf);
            gi = __ldcg(gxt + (size_t)(1 * HID + jgf) * BATCH + bgf);
            go = __ldcg(gxt + (size_t)(2 * HID + jgf) * BATCH + bgf);
            gc = __ldcg(gxt + (size_t)(3 * HID + jgf) * BATCH + bgf);
        }

        unsigned long long acc[32];        // [jj*4+gate], f32x2 over k-parity
#pragma unroll
        for (int i = 0; i < 32; i++) acc[i] = 0ull;

        const float4* hq = &g_hq[cur][grp][0];
#pragma unroll
        for (int it = 0; it < 8; it++) {
            U4 hh; hh.f = __ldcg(hq + (ko * 8 + it) * 16 + b);
#pragma unroll
            for (int jj = 0; jj < 8; jj++) {
                int rbase = ((jh * 8 + jj) << 2);
#pragma unroll
                for (int gate = 0; gate < 4; gate++) {
                    U4 w; w.f = ws4[(rbase + gate) * 128 + ko * 8 + it];
                    fma2(acc[jj * 4 + gate], hh.u.x, w.u.x);
                    fma2(acc[jj * 4 + gate], hh.u.y, w.u.y);
                }
            }
        }

        // partials: red4[(ko*16 + j_loc)*16 + b] = {f,i,o,c}
#pragma unroll
        for (int jj = 0; jj < 8; jj++) {
            red4[(ko * 16 + jh * 8 + jj) * 16 + b] =
                make_float4(usum(acc[jj * 4 + 0]), usum(acc[jj * 4 + 1]),
                            usum(acc[jj * 4 + 2]), usum(acc[jj * 4 + 3]));
        }
        __syncthreads();

        if (fin) {
            float4 s = red4[(0 * 16 + fj) * 16 + fb];
#pragma unroll
            for (int ks = 1; ks < 16; ks++) {
                float4 p = red4[(ks * 16 + fj) * 16 + fb];
                s.x += p.x; s.y += p.y; s.z += p.z; s.w += p.w;
            }
            float F = fsig(s.x + gf);
            float I = fsig(s.y + gi);
            float O = fsig(s.z + go);
            C = F * C + I * ftanh(s.w + gc);
            hv = O * ftanh(C);
            ((float*)&g_hq[cur ^ 1][grp][(jgf >> 2) * 16 + fb])[jgf & 3] = hv;
        }

        gbarg(grp, tid, base + 2 + t);
        cur ^= 1;
    }

    if (fin) g_hbt[(size_t)jgf * BATCH + bgf] = hv;   // [k][b] for fc
    if (bx == 0 && tid == 0) g_epoch = base + SEQ + 8;
}

// ============================================================================
// Kernel 3: out[b][n] = h[b] . fc_weight[n] + fc_bias[n]   (frozen)
// ============================================================================
__global__ __launch_bounds__(256, 1) void fc_kernel(
    const float* __restrict__ fcw, const float* __restrict__ fcb,
    float* __restrict__ out)
{
    extern __shared__ float hb2[];   // 512 rows x 68 floats
    const int tid = threadIdx.x;
    for (int i = tid; i < HID * 16; i += 256) {
        int k = i >> 4, q = i & 15;
        ((float4*)(hb2 + k * 68))[q] = ((const float4*)g_hbt)[i];
    }
    __syncthreads();

    const int warp = tid >> 5, lane = tid & 31;
    const int wglobal = blockIdx.x * 8 + warp;
    const int nw = gridDim.x * 8;

    for (int n = wglobal; n < NCLS; n += nw) {
        unsigned long long acc[32];
#pragma unroll
        for (int i = 0; i < 32; i++) acc[i] = 0ull;
        const float* wrow = fcw + (size_t)n * HID;
#pragma unroll
        for (int kk = 0; kk < 16; kk++) {
            int k = kk * 32 + lane;
            unsigned long long ww = pack2(wrow[k]);
            const float4* hrow = (const float4*)(hb2 + k * 68);
#pragma unroll
            for (int q = 0; q < 16; q++) {
                U4 hh; hh.f = hrow[q];
                fma2(acc[2 * q],     ww, hh.u.x);
                fma2(acc[2 * q + 1], ww, hh.u.y);
            }
        }
        float bias = fcb[n];
#pragma unroll
        for (int p = 0; p < 32; p++) {
            unsigned long long v = acc[p];
            add2(v, __shfl_xor_sync(0xffffffffu, v, 16));
            add2(v, __shfl_xor_sync(0xffffffffu, v, 8));
            add2(v, __shfl_xor_sync(0xffffffffu, v, 4));
            add2(v, __shfl_xor_sync(0xffffffffu, v, 2));
            add2(v, __shfl_xor_sync(0xffffffffu, v, 1));
            if (lane == 0) {
                U2 u; u.u = v;
                out[(size_t)(2 * p) * NCLS + n]     = u.f.x + bias;
                out[(size_t)(2 * p + 1) * NCLS + n] = u.f.y + bias;
            }
        }
    }
}

// ============================================================================
extern "C" void kernel_launch(void* const* d_in, const int* in_sizes, int n_in,
                              void* d_out, int out_size)
{
    const int*   x   = (const int*)d_in[0];
    const float* emb = (const float*)d_in[1];
    const float* W   = (const float*)d_in[2];
    const float* Wb  = (const float*)d_in[3];
    const float* fcw = (const float*)d_in[4];
    const float* fcb = (const float*)d_in[5];
    float* out = (float*)d_out;

    // ws 128 KB + red4 64 KB = 196608 B
    static const size_t lstm_smem = (size_t)64 * HID * 4 + (size_t)4096 * 16;
    static const size_t fc_smem = (size_t)HID * 68 * 4;      // 139264
    cudaFuncSetAttribute(lstm_kernel, cudaFuncAttributeMaxDynamicSharedMemorySize,
                         (int)lstm_smem);
    cudaFuncSetAttribute(fc_kernel, cudaFuncAttributeMaxDynamicSharedMemorySize,
                         (int)fc_smem);

    dim3 g1(SEQ * BATCH / 128, NG / 128);
    gx_kernel<<<g1, 256>>>(x, emb, W, Wb);

    lstm_kernel<<<NCTA, 512, lstm_smem>>>(W);

    fc_kernel<<<148, 256, fc_smem>>>(fcw, fcb, out);
}

// round 15
// speedup vs baseline: 1.2013x; 1.0552x over previous
#include <cuda_runtime.h>
#include <math.h>

#define EMBD 256
#define HID  512
#define BATCH 64
#define SEQ  512
#define NG   2048      // 4*HID
#define WROW 768       // EMB+HID
#define NCLS 50257
#define NCTA 128
#define GSIZE 32       // CTAs per group
#define NGROUP 4       // independent batch groups
#define GBATCH 16      // batches per group

// ---------------- scratch (static device globals; no cudaMalloc allowed) ----
__device__ float g_Gx[(size_t)SEQ * NG * BATCH];   // [t][g][b]  (transposed)
// per-group h, quad layout: g_hq[buf][grp][kq*16 + b_loc] = h[b][4kq..4kq+3]
__device__ float4 g_hq[2][NGROUP][128 * 16];
__device__ float g_hbt[HID * BATCH];               // final hidden, [k][b]
__device__ volatile unsigned g_arrive[NCTA * 32];  // padded flag at bx*32
__device__ unsigned g_epoch;                       // bumped each launch

// ---------------- packed f32x2 helpers --------------------------------------
__device__ __forceinline__ void fma2(unsigned long long& d,
                                     unsigned long long a,
                                     unsigned long long b) {
    asm("fma.rn.f32x2 %0, %1, %2, %0;" : "+l"(d) : "l"(a), "l"(b));
}
__device__ __forceinline__ unsigned long long pack2(float v) {
    unsigned long long r;
    asm("mov.b64 %0, {%1, %1};" : "=l"(r) : "f"(v));
    return r;
}
__device__ __forceinline__ void add2(unsigned long long& d, unsigned long long a) {
    asm("add.rn.f32x2 %0, %0, %1;" : "+l"(d) : "l"(a));
}
union U2 { float2 f; unsigned long long u; };
union U4 { float4 f; ulonglong2 u; };
__device__ __forceinline__ float usum(unsigned long long v) {
    U2 x; x.u = v; return x.f.x + x.f.y;
}
__device__ __forceinline__ float fsig(float x) {
    return __fdividef(1.f, 1.f + __expf(-x));
}
__device__ __forceinline__ float ftanh(float x) {
    return __fdividef(2.f, 1.f + __expf(-2.f * x)) - 1.f;
}

// ============================================================================
// Kernel 1: Gx = emb[x] . WxT + bias, output TRANSPOSED as [t][g][b]. (frozen)
// ============================================================================
__global__ __launch_bounds__(256) void gx_kernel(
    const int* __restrict__ x, const float* __restrict__ emb,
    const float* __restrict__ W, const float* __restrict__ bias)
{
    __shared__ float As[16][128];
    __shared__ float Bs[16][128];
    __shared__ int   tok[128];

    const int tid = threadIdx.x;
    const int m0 = blockIdx.x * 128;
    const int n0 = blockIdx.y * 128;

    if (tid < 128) {
        int m = m0 + tid;
        tok[tid] = x[(m & 63) * SEQ + (m >> 6)];
    }
    __syncthreads();

    const int lm = tid & 127, lq = tid >> 7;
    const int tx = tid & 15,  ty = tid >> 4;

    float acc[8][8];
#pragma unroll
    for (int i = 0; i < 8; i++)
#pragma unroll
        for (int jj = 0; jj < 8; jj++) acc[i][jj] = 0.f;

    float4 ra0, ra1, rb0, rb1;
    {
        const float* arow = emb + (size_t)tok[lm] * EMBD;
        ra0 = *(const float4*)(arow + lq * 4);
        ra1 = *(const float4*)(arow + 8 + lq * 4);
        const float* brow = W + (size_t)(n0 + lm) * WROW;
        rb0 = *(const float4*)(brow + lq * 4);
        rb1 = *(const float4*)(brow + 8 + lq * 4);
    }

    for (int kt = 0; kt < 16; kt++) {
        As[lq * 4 + 0][lm] = ra0.x; As[lq * 4 + 1][lm] = ra0.y;
        As[lq * 4 + 2][lm] = ra0.z; As[lq * 4 + 3][lm] = ra0.w;
        As[8 + lq * 4 + 0][lm] = ra1.x; As[8 + lq * 4 + 1][lm] = ra1.y;
        As[8 + lq * 4 + 2][lm] = ra1.z; As[8 + lq * 4 + 3][lm] = ra1.w;
        Bs[lq * 4 + 0][lm] = rb0.x; Bs[lq * 4 + 1][lm] = rb0.y;
        Bs[lq * 4 + 2][lm] = rb0.z; Bs[lq * 4 + 3][lm] = rb0.w;
        Bs[8 + lq * 4 + 0][lm] = rb1.x; Bs[8 + lq * 4 + 1][lm] = rb1.y;
        Bs[8 + lq * 4 + 2][lm] = rb1.z; Bs[8 + lq * 4 + 3][lm] = rb1.w;
        __syncthreads();

        if (kt < 15) {
            int k0 = (kt + 1) * 16;
            const float* arow = emb + (size_t)tok[lm] * EMBD + k0;
            ra0 = *(const float4*)(arow + lq * 4);
            ra1 = *(const float4*)(arow + 8 + lq * 4);
            const float* brow = W + (size_t)(n0 + lm) * WROW + k0;
            rb0 = *(const float4*)(brow + lq * 4);
            rb1 = *(const float4*)(brow + 8 + lq * 4);
        }

#pragma unroll
        for (int k = 0; k < 16; k++) {
            float4 aL = *(const float4*)&As[k][ty * 4];
            float4 aH = *(const float4*)&As[k][64 + ty * 4];
            float4 bL = *(const float4*)&Bs[k][tx * 4];
            float4 bH = *(const float4*)&Bs[k][64 + tx * 4];
            float av[8] = {aL.x, aL.y, aL.z, aL.w, aH.x, aH.y, aH.z, aH.w};
            float bv[8] = {bL.x, bL.y, bL.z, bL.w, bH.x, bH.y, bH.z, bH.w};
#pragma unroll
            for (int i = 0; i < 8; i++)
#pragma unroll
                for (int jj = 0; jj < 8; jj++)
                    acc[i][jj] = fmaf(av[i], bv[jj], acc[i][jj]);
        }
        __syncthreads();
    }

    {
        float4 biL = *(const float4*)(bias + n0 + tx * 4);
        float4 biH = *(const float4*)(bias + n0 + 64 + tx * 4);
        float bl[8] = {biL.x, biL.y, biL.z, biL.w, biH.x, biH.y, biH.z, biH.w};
#pragma unroll
        for (int r = 0; r < 8; r++)
#pragma unroll
            for (int cc = 0; cc < 8; cc++) acc[r][cc] += bl[cc];
    }

    float* T = &As[0][0];
    for (int s = 0; s < 8; s++) {
        __syncthreads();
        int txg = s & 3;
        int jbase = (s < 4) ? 0 : 4;
        if ((tx >> 2) == txg) {
#pragma unroll
            for (int q = 0; q < 4; q++) {
                int cl = (tx & 3) * 4 + q;
#pragma unroll
                for (int r = 0; r < 8; r++) {
                    int m_loc = (r >> 2) * 64 + ty * 4 + (r & 3);
                    T[cl * 128 + m_loc] = acc[r][jbase + q];
                }
            }
        }
        __syncthreads();
#pragma unroll
        for (int w = 0; w < 2; w++) {
            int v = tid + w * 256;
            int row = v >> 4;
            int within = v & 15;
            int cl = row >> 1, tl = row & 1;
            float4 val = *(float4*)&T[cl * 128 + tl * 64 + within * 4];
            int t = (m0 >> 6) + tl;
            int gcol = n0 + s * 16 + cl;
            *(float4*)&g_Gx[((size_t)t * NG + gcol) * BATCH + within * 4] = val;
        }
    }
}

// ============================================================================
// Kernel 2: persistent LSTM — 4 independent groups of 32 CTAs (round-13
//   structure), with:
//   - split-phase group barrier: arrive after h write, prefetch next-step gx,
//     then spin-wait (gx DRAM latency overlaps barrier drain)
//   - 2-deep rotating prefetch of h quads in the compute loop
//   - packed add2 finalize reduction
// ============================================================================
__global__ __launch_bounds__(512, 1) void lstm_kernel(const float* __restrict__ W)
{
    extern __shared__ float smem[];
    float* ws = smem;                               // 64 x 512 f (128 KB)
    float4* red4 = (float4*)(smem + 64 * HID);      // 4096 f4  (64 KB)

    const int tid  = threadIdx.x;
    const int bx   = blockIdx.x;
    const int grp  = bx >> 5;
    const int c    = bx & 31;
    const int l    = tid & 31;
    const int ko   = tid >> 5;             // warp: k-slice [ko*32, ko*32+32)
    const int b    = l & 15;               // batch within group
    const int jh   = l >> 4;               // j-half (8 j each)
    const unsigned base = g_epoch;

    const bool fin = (tid < 256);
    const int fj = tid >> 4;               // 0..15 (valid when fin)
    const int fb = tid & 15;
    const int jgf = c * 16 + fj;           // global j of finalizer
    const int bgf = grp * GBATCH + fb;     // global batch of finalizer

    // stationary weights: ws[(j_loc*4+gate)*512 + k]
    for (int i = tid; i < 64 * HID; i += 512) {
        int row = i >> 9;                  // j_loc*4+gate
        int k   = i & 511;
        int j_loc = row >> 2, gate = row & 3;
        ws[i] = W[(size_t)(gate * HID + c * 16 + j_loc) * WROW + EMBD + k];
    }
    // zero this group's h buffer 0 (CTA 0 of the group)
    if (c == 0) {
        for (int i = tid; i < 128 * 16; i += 512)
            g_hq[0][grp][i] = make_float4(0.f, 0.f, 0.f, 0.f);
    }

    // full split barrier for init
    __threadfence();
    __syncthreads();
    if (tid == 0) g_arrive[(grp * GSIZE + c) * 32] = base + 1;
    if (tid < GSIZE) {
        while (g_arrive[(grp * GSIZE + tid) * 32] < base + 1) { }
    }
    __syncthreads();

    const float4* ws4 = (const float4*)ws;        // row*128 + kq
    float C = 0.f, hv = 0.f;
    int cur = 0;

    // prefetch gx for t = 0
    float gf, gi, go, gc;
    if (fin) {
        const float* gxt = g_Gx;
        gf = __ldcg(gxt + (size_t)(0 * HID + jgf) * BATCH + bgf);
        gi = __ldcg(gxt + (size_t)(1 * HID + jgf) * BATCH + bgf);
        go = __ldcg(gxt + (size_t)(2 * HID + jgf) * BATCH + bgf);
        gc = __ldcg(gxt + (size_t)(3 * HID + jgf) * BATCH + bgf);
    }

    for (int t = 0; t < SEQ; t++) {
        unsigned long long acc[32];        // [jj*4+gate], f32x2 over k-parity
#pragma unroll
        for (int i = 0; i < 32; i++) acc[i] = 0ull;

        const float4* hq = &g_hq[cur][grp][0];
        // 2-deep rotating prefetch of h quads
        U4 h0, h1;
        h0.f = __ldcg(hq + (ko * 8 + 0) * 16 + b);
        h1.f = __ldcg(hq + (ko * 8 + 1) * 16 + b);
#pragma unroll
        for (int it = 0; it < 8; it++) {
            U4 hh = h0;
            h0 = h1;
            if (it < 6) h1.f = __ldcg(hq + (ko * 8 + it + 2) * 16 + b);
#pragma unroll
            for (int jj = 0; jj < 8; jj++) {
                int rbase = ((jh * 8 + jj) << 2);
#pragma unroll
                for (int gate = 0; gate < 4; gate++) {
                    U4 w; w.f = ws4[(rbase + gate) * 128 + ko * 8 + it];
                    fma2(acc[jj * 4 + gate], hh.u.x, w.u.x);
                    fma2(acc[jj * 4 + gate], hh.u.y, w.u.y);
                }
            }
        }

        // partials: red4[(ko*16 + j_loc)*16 + b] = {f,i,o,c}
#pragma unroll
        for (int jj = 0; jj < 8; jj++) {
            red4[(ko * 16 + jh * 8 + jj) * 16 + b] =
                make_float4(usum(acc[jj * 4 + 0]), usum(acc[jj * 4 + 1]),
                            usum(acc[jj * 4 + 2]), usum(acc[jj * 4 + 3]));
        }
        __syncthreads();

        if (fin) {
            U4 s; s.f = red4[(0 * 16 + fj) * 16 + fb];
#pragma unroll
            for (int ks = 1; ks < 16; ks++) {
                U4 p; p.f = red4[(ks * 16 + fj) * 16 + fb];
                add2(s.u.x, p.u.x);
                add2(s.u.y, p.u.y);
            }
            float F = fsig(s.f.x + gf);
            float I = fsig(s.f.y + gi);
            float O = fsig(s.f.z + go);
            C = F * C + I * ftanh(s.f.w + gc);
            hv = O * ftanh(C);
            ((float*)&g_hq[cur ^ 1][grp][(jgf >> 2) * 16 + fb])[jgf & 3] = hv;
        }

        // --- split-phase barrier: arrive, prefetch next gx, wait -----------
        __threadfence();
        __syncthreads();                       // all h writes done + visible
        if (tid == 0) g_arrive[(grp * GSIZE + c) * 32] = base + 2 + t;

        if (fin && t + 1 < SEQ) {              // overlap gx DRAM latency
            const float* gxt = g_Gx + (size_t)(t + 1) * NG * BATCH;
            gf = __ldcg(gxt + (size_t)(0 * HID + jgf) * BATCH + bgf);
            gi = __ldcg(gxt + (size_t)(1 * HID + jgf) * BATCH + bgf);
            go = __ldcg(gxt + (size_t)(2 * HID + jgf) * BATCH + bgf);
            gc = __ldcg(gxt + (size_t)(3 * HID + jgf) * BATCH + bgf);
        }

        if (tid < GSIZE) {
            while (g_arrive[(grp * GSIZE + tid) * 32] < base + 2 + t) { }
        }
        __syncthreads();
        cur ^= 1;
    }

    if (fin) g_hbt[(size_t)jgf * BATCH + bgf] = hv;   // [k][b] for fc
    if (bx == 0 && tid == 0) g_epoch = base + SEQ + 8;
}

// ============================================================================
// Kernel 3: out[b][n] = h[b] . fc_weight[n] + fc_bias[n]   (frozen)
// ============================================================================
__global__ __launch_bounds__(256, 1) void fc_kernel(
    const float* __restrict__ fcw, const float* __restrict__ fcb,
    float* __restrict__ out)
{
    extern __shared__ float hb2[];   // 512 rows x 68 floats
    const int tid = threadIdx.x;
    for (int i = tid; i < HID * 16; i += 256) {
        int k = i >> 4, q = i & 15;
        ((float4*)(hb2 + k * 68))[q] = ((const float4*)g_hbt)[i];
    }
    __syncthreads();

    const int warp = tid >> 5, lane = tid & 31;
    const int wglobal = blockIdx.x * 8 + warp;
    const int nw = gridDim.x * 8;

    for (int n = wglobal; n < NCLS; n += nw) {
        unsigned long long acc[32];
#pragma unroll
        for (int i = 0; i < 32; i++) acc[i] = 0ull;
        const float* wrow = fcw + (size_t)n * HID;
#pragma unroll
        for (int kk = 0; kk < 16; kk++) {
            int k = kk * 32 + lane;
            unsigned long long ww = pack2(wrow[k]);
            const float4* hrow = (const float4*)(hb2 + k * 68);
#pragma unroll
            for (int q = 0; q < 16; q++) {
                U4 hh; hh.f = hrow[q];
                fma2(acc[2 * q],     ww, hh.u.x);
                fma2(acc[2 * q + 1], ww, hh.u.y);
            }
        }
        float bias = fcb[n];
#pragma unroll
        for (int p = 0; p < 32; p++) {
            unsigned long long v = acc[p];
            add2(v, __shfl_xor_sync(0xffffffffu, v, 16));
            add2(v, __shfl_xor_sync(0xffffffffu, v, 8));
            add2(v, __shfl_xor_sync(0xffffffffu, v, 4));
            add2(v, __shfl_xor_sync(0xffffffffu, v, 2));
            add2(v, __shfl_xor_sync(0xffffffffu, v, 1));
            if (lane == 0) {
                U2 u; u.u = v;
                out[(size_t)(2 * p) * NCLS + n]     = u.f.x + bias;
                out[(size_t)(2 * p + 1) * NCLS + n] = u.f.y + bias;
            }
        }
    }
}

// ============================================================================
extern "C" void kernel_launch(void* const* d_in, const int* in_sizes, int n_in,
                              void* d_out, int out_size)
{
    const int*   x   = (const int*)d_in[0];
    const float* emb = (const float*)d_in[1];
    const float* W   = (const float*)d_in[2];
    const float* Wb  = (const float*)d_in[3];
    const float* fcw = (const float*)d_in[4];
    const float* fcb = (const float*)d_in[5];
    float* out = (float*)d_out;

    // ws 128 KB + red4 64 KB = 196608 B
    static const size_t lstm_smem = (size_t)64 * HID * 4 + (size_t)4096 * 16;
    static const size_t fc_smem = (size_t)HID * 68 * 4;      // 139264
    cudaFuncSetAttribute(lstm_kernel, cudaFuncAttributeMaxDynamicSharedMemorySize,
                         (int)lstm_smem);
    cudaFuncSetAttribute(fc_kernel, cudaFuncAttributeMaxDynamicSharedMemorySize,
                         (int)fc_smem);

    dim3 g1(SEQ * BATCH / 128, NG / 128);
    gx_kernel<<<g1, 256>>>(x, emb, W, Wb);

    lstm_kernel<<<NCTA, 512, lstm_smem>>>(W);

    fc_kernel<<<148, 256, fc_smem>>>(fcw, fcb, out);
}

// round 17
// speedup vs baseline: 1.2784x; 1.0642x over previous
#include <cuda_runtime.h>
#include <math.h>

#define EMBD 256
#define HID  512
#define BATCH 64
#define SEQ  512
#define NG   2048      // 4*HID
#define WROW 768       // EMB+HID
#define NCLS 50257
#define NCTA 128
#define GSIZE 32       // CTAs per group
#define NGROUP 4       // independent batch groups
#define GBATCH 16      // batches per group

// ---------------- scratch (static device globals; no cudaMalloc allowed) ----
__device__ float g_Gx[(size_t)SEQ * NG * BATCH];   // [t][g][b]  (transposed)
__device__ float4 g_hq[2][NGROUP][128 * 16];       // per-group h quads
__device__ float g_hbt[HID * BATCH];               // final hidden, [k][b]
__device__ volatile unsigned g_arrive[NCTA * 32];  // padded flag at bx*32
__device__ unsigned g_epoch;                       // bumped each launch

// ---------------- packed f32x2 helpers --------------------------------------
__device__ __forceinline__ void fma2(unsigned long long& d,
                                     unsigned long long a,
                                     unsigned long long b) {
    asm("fma.rn.f32x2 %0, %1, %2, %0;" : "+l"(d) : "l"(a), "l"(b));
}
__device__ __forceinline__ unsigned long long pack2(float v) {
    unsigned long long r;
    asm("mov.b64 %0, {%1, %1};" : "=l"(r) : "f"(v));
    return r;
}
__device__ __forceinline__ void add2(unsigned long long& d, unsigned long long a) {
    asm("add.rn.f32x2 %0, %0, %1;" : "+l"(d) : "l"(a));
}
union U2 { float2 f; unsigned long long u; };
union U4 { float4 f; ulonglong2 u; };
__device__ __forceinline__ float usum(unsigned long long v) {
    U2 x; x.u = v; return x.f.x + x.f.y;
}
__device__ __forceinline__ float fsig(float x) {
    return __fdividef(1.f, 1.f + __expf(-x));
}
__device__ __forceinline__ float ftanh(float x) {
    return __fdividef(2.f, 1.f + __expf(-2.f * x)) - 1.f;
}

// ============================================================================
// Kernel 1: Gx = emb[x] . WxT + bias, output TRANSPOSED as [t][g][b].
//   128x128 tile, BK=16, 8x8/thread, scalar FFMA (proven 725us body, frozen).
// ============================================================================
__global__ __launch_bounds__(256) void gx_kernel(
    const int* __restrict__ x, const float* __restrict__ emb,
    const float* __restrict__ W, const float* __restrict__ bias)
{
    __shared__ float As[16][128];
    __shared__ float Bs[16][128];
    __shared__ int   tok[128];

    const int tid = threadIdx.x;
    const int m0 = blockIdx.x * 128;
    const int n0 = blockIdx.y * 128;

    if (tid < 128) {
        int m = m0 + tid;
        tok[tid] = x[(m & 63) * SEQ + (m >> 6)];
    }
    __syncthreads();

    const int lm = tid & 127, lq = tid >> 7;
    const int tx = tid & 15,  ty = tid >> 4;

    float acc[8][8];
#pragma unroll
    for (int i = 0; i < 8; i++)
#pragma unroll
        for (int jj = 0; jj < 8; jj++) acc[i][jj] = 0.f;

    float4 ra0, ra1, rb0, rb1;
    {
        const float* arow = emb + (size_t)tok[lm] * EMBD;
        ra0 = *(const float4*)(arow + lq * 4);
        ra1 = *(const float4*)(arow + 8 + lq * 4);
        const float* brow = W + (size_t)(n0 + lm) * WROW;
        rb0 = *(const float4*)(brow + lq * 4);
        rb1 = *(const float4*)(brow + 8 + lq * 4);
    }

    for (int kt = 0; kt < 16; kt++) {
        As[lq * 4 + 0][lm] = ra0.x; As[lq * 4 + 1][lm] = ra0.y;
        As[lq * 4 + 2][lm] = ra0.z; As[lq * 4 + 3][lm] = ra0.w;
        As[8 + lq * 4 + 0][lm] = ra1.x; As[8 + lq * 4 + 1][lm] = ra1.y;
        As[8 + lq * 4 + 2][lm] = ra1.z; As[8 + lq * 4 + 3][lm] = ra1.w;
        Bs[lq * 4 + 0][lm] = rb0.x; Bs[lq * 4 + 1][lm] = rb0.y;
        Bs[lq * 4 + 2][lm] = rb0.z; Bs[lq * 4 + 3][lm] = rb0.w;
        Bs[8 + lq * 4 + 0][lm] = rb1.x; Bs[8 + lq * 4 + 1][lm] = rb1.y;
        Bs[8 + lq * 4 + 2][lm] = rb1.z; Bs[8 + lq * 4 + 3][lm] = rb1.w;
        __syncthreads();

        if (kt < 15) {
            int k0 = (kt + 1) * 16;
            const float* arow = emb + (size_t)tok[lm] * EMBD + k0;
            ra0 = *(const float4*)(arow + lq * 4);
            ra1 = *(const float4*)(arow + 8 + lq * 4);
            const float* brow = W + (size_t)(n0 + lm) * WROW + k0;
            rb0 = *(const float4*)(brow + lq * 4);
            rb1 = *(const float4*)(brow + 8 + lq * 4);
        }

#pragma unroll
        for (int k = 0; k < 16; k++) {
            float4 aL = *(const float4*)&As[k][ty * 4];
            float4 aH = *(const float4*)&As[k][64 + ty * 4];
            float4 bL = *(const float4*)&Bs[k][tx * 4];
            float4 bH = *(const float4*)&Bs[k][64 + tx * 4];
            float av[8] = {aL.x, aL.y, aL.z, aL.w, aH.x, aH.y, aH.z, aH.w};
            float bv[8] = {bL.x, bL.y, bL.z, bL.w, bH.x, bH.y, bH.z, bH.w};
#pragma unroll
            for (int i = 0; i < 8; i++)
#pragma unroll
                for (int jj = 0; jj < 8; jj++)
                    acc[i][jj] = fmaf(av[i], bv[jj], acc[i][jj]);
        }
        __syncthreads();
    }

    {
        float4 biL = *(const float4*)(bias + n0 + tx * 4);
        float4 biH = *(const float4*)(bias + n0 + 64 + tx * 4);
        float bl[8] = {biL.x, biL.y, biL.z, biL.w, biH.x, biH.y, biH.z, biH.w};
#pragma unroll
        for (int r = 0; r < 8; r++)
#pragma unroll
            for (int cc = 0; cc < 8; cc++) acc[r][cc] += bl[cc];
    }

    float* T = &As[0][0];
    for (int s = 0; s < 8; s++) {
        __syncthreads();
        int txg = s & 3;
        int jbase = (s < 4) ? 0 : 4;
        if ((tx >> 2) == txg) {
#pragma unroll
            for (int q = 0; q < 4; q++) {
                int cl = (tx & 3) * 4 + q;
#pragma unroll
                for (int r = 0; r < 8; r++) {
                    int m_loc = (r >> 2) * 64 + ty * 4 + (r & 3);
                    T[cl * 128 + m_loc] = acc[r][jbase + q];
                }
            }
        }
        __syncthreads();
#pragma unroll
        for (int w = 0; w < 2; w++) {
            int v = tid + w * 256;
            int row = v >> 4;
            int within = v & 15;
            int cl = row >> 1, tl = row & 1;
            float4 val = *(float4*)&T[cl * 128 + tl * 64 + within * 4];
            int t = (m0 >> 6) + tl;
            int gcol = n0 + s * 16 + cl;
            *(float4*)&g_Gx[((size_t)t * NG + gcol) * BATCH + within * 4] = val;
        }
    }
}

// ============================================================================
// Kernel 2: persistent LSTM — 4 independent groups of 32 CTAs; FINE-GRAINED
//   producer/consumer sync: warp ko consumes h for j in [32ko,32ko+32),
//   produced by CTAs {2ko, 2ko+1} of the group — so each warp waits only on
//   its 2 producers' flags instead of a group-wide barrier. The post-partials
//   __syncthreads makes the CTA observe all 32 producers before finalize
//   overwrites the previous buffer (2-buffer safety preserved).
// ============================================================================
__global__ __launch_bounds__(512, 1) void lstm_kernel(const float* __restrict__ W)
{
    extern __shared__ float smemf[];
    float* ws = smemf;                               // 64 x 512 f (128 KB)
    float4* red4 = (float4*)(smemf + 64 * HID);      // 4096 f4  (64 KB)

    const int tid  = threadIdx.x;
    const int bx   = blockIdx.x;
    const int grp  = bx >> 5;
    const int c    = bx & 31;
    const int l    = tid & 31;
    const int ko   = tid >> 5;             // warp: k-slice [ko*32, ko*32+32)
    const int b    = l & 15;               // batch within group
    const int jh   = l >> 4;               // j-half (8 j each)
    const unsigned base = g_epoch;

    const bool fin = (tid < 256);
    const int fj = tid >> 4;               // 0..15 (valid when fin)
    const int fb = tid & 15;
    const int jgf = c * 16 + fj;           // global j of finalizer
    const int bgf = grp * GBATCH + fb;     // global batch of finalizer

    // stationary weights: ws[(j_loc*4+gate)*512 + k]
    for (int i = tid; i < 64 * HID; i += 512) {
        int row = i >> 9;
        int k   = i & 511;
        int j_loc = row >> 2, gate = row & 3;
        ws[i] = W[(size_t)(gate * HID + c * 16 + j_loc) * WROW + EMBD + k];
    }
    if (c == 0) {
        for (int i = tid; i < 128 * 16; i += 512)
            g_hq[0][grp][i] = make_float4(0.f, 0.f, 0.f, 0.f);
    }

    // init barrier (group-wide, once)
    __threadfence();
    __syncthreads();
    if (tid == 0) g_arrive[(grp * GSIZE + c) * 32] = base + 1;
    if (tid < GSIZE) {
        while (g_arrive[(grp * GSIZE + tid) * 32] < base + 1) { }
    }
    __syncthreads();

    const float4* ws4 = (const float4*)ws;
    float C = 0.f, hv = 0.f;
    int cur = 0;

    // prefetch gx for t = 0
    float gf, gi, go, gc;
    if (fin) {
        const float* gxt = g_Gx;
        gf = __ldcg(gxt + (size_t)(0 * HID + jgf) * BATCH + bgf);
        gi = __ldcg(gxt + (size_t)(1 * HID + jgf) * BATCH + bgf);
        go = __ldcg(gxt + (size_t)(2 * HID + jgf) * BATCH + bgf);
        gc = __ldcg(gxt + (size_t)(3 * HID + jgf) * BATCH + bgf);
    }

    for (int t = 0; t < SEQ; t++) {
        // per-warp wait: only this warp's 2 producer CTAs must have published
        // h(t) (flag value base+1+t: init for t=0, step-(t-1) arrive after).
        if (l < 2) {
            const int pf = (grp * GSIZE + 2 * ko + l) * 32;
            while (g_arrive[pf] < base + 1 + t) { }
        }
        __syncwarp();

        unsigned long long acc[32];        // [jj*4+gate], f32x2 over k-parity
#pragma unroll
        for (int i = 0; i < 32; i++) acc[i] = 0ull;

        const float4* hq = &g_hq[cur][grp][0];
        U4 h0, h1;
        h0.f = __ldcg(hq + (ko * 8 + 0) * 16 + b);
        h1.f = __ldcg(hq + (ko * 8 + 1) * 16 + b);
#pragma unroll
        for (int it = 0; it < 8; it++) {
            U4 hh = h0;
            h0 = h1;
            if (it < 6) h1.f = __ldcg(hq + (ko * 8 + it + 2) * 16 + b);
#pragma unroll
            for (int jj = 0; jj < 8; jj++) {
                int rbase = ((jh * 8 + jj) << 2);
#pragma unroll
                for (int gate = 0; gate < 4; gate++) {
                    U4 w; w.f = ws4[(rbase + gate) * 128 + ko * 8 + it];
                    fma2(acc[jj * 4 + gate], hh.u.x, w.u.x);
                    fma2(acc[jj * 4 + gate], hh.u.y, w.u.y);
                }
            }
        }

        // partials: red4[(ko*16 + j_loc)*16 + b] = {f,i,o,c}
#pragma unroll
        for (int jj = 0; jj < 8; jj++) {
            red4[(ko * 16 + jh * 8 + jj) * 16 + b] =
                make_float4(usum(acc[jj * 4 + 0]), usum(acc[jj * 4 + 1]),
                            usum(acc[jj * 4 + 2]), usum(acc[jj * 4 + 3]));
        }
        __syncthreads();   // joins all warps => all 32 producers of step t seen

        if (fin) {
            U4 s; s.f = red4[(0 * 16 + fj) * 16 + fb];
#pragma unroll
            for (int ks = 1; ks < 16; ks++) {
                U4 p; p.f = red4[(ks * 16 + fj) * 16 + fb];
                add2(s.u.x, p.u.x);
                add2(s.u.y, p.u.y);
            }
            float F = fsig(s.f.x + gf);
            float I = fsig(s.f.y + gi);
            float O = fsig(s.f.z + go);
            C = F * C + I * ftanh(s.f.w + gc);
            hv = O * ftanh(C);
            ((float*)&g_hq[cur ^ 1][grp][(jgf >> 2) * 16 + fb])[jgf & 3] = hv;
        }

        // publish: fence + per-CTA arrive; NO group-wide wait.
        __threadfence();
        __syncthreads();                       // h writes done CTA-wide
        if (tid == 0) g_arrive[(grp * GSIZE + c) * 32] = base + 2 + t;

        if (fin && t + 1 < SEQ) {              // overlap gx DRAM latency
            const float* gxt = g_Gx + (size_t)(t + 1) * NG * BATCH;
            gf = __ldcg(gxt + (size_t)(0 * HID + jgf) * BATCH + bgf);
            gi = __ldcg(gxt + (size_t)(1 * HID + jgf) * BATCH + bgf);
            go = __ldcg(gxt + (size_t)(2 * HID + jgf) * BATCH + bgf);
            gc = __ldcg(gxt + (size_t)(3 * HID + jgf) * BATCH + bgf);
        }
        __syncthreads();   // red4 safe to overwrite next step (finalize done)
        cur ^= 1;
    }

    if (fin) g_hbt[(size_t)jgf * BATCH + bgf] = hv;   // [k][b] for fc
    if (bx == 0 && tid == 0) g_epoch = base + SEQ + 8;
}

// ============================================================================
// Kernel 3: out[b][n] = h[b] . fc_weight[n] + fc_bias[n]   (frozen)
// ============================================================================
__global__ __launch_bounds__(256, 1) void fc_kernel(
    const float* __restrict__ fcw, const float* __restrict__ fcb,
    float* __restrict__ out)
{
    extern __shared__ float hb2[];   // 512 rows x 68 floats
    const int tid = threadIdx.x;
    for (int i = tid; i < HID * 16; i += 256) {
        int k = i >> 4, q = i & 15;
        ((float4*)(hb2 + k * 68))[q] = ((const float4*)g_hbt)[i];
    }
    __syncthreads();

    const int warp = tid >> 5, lane = tid & 31;
    const int wglobal = blockIdx.x * 8 + warp;
    const int nw = gridDim.x * 8;

    for (int n = wglobal; n < NCLS; n += nw) {
        unsigned long long acc[32];
#pragma unroll
        for (int i = 0; i < 32; i++) acc[i] = 0ull;
        const float* wrow = fcw + (size_t)n * HID;
#pragma unroll
        for (int kk = 0; kk < 16; kk++) {
            int k = kk * 32 + lane;
            unsigned long long ww = pack2(wrow[k]);
            const float4* hrow = (const float4*)(hb2 + k * 68);
#pragma unroll
            for (int q = 0; q < 16; q++) {
                U4 hh; hh.f = hrow[q];
                fma2(acc[2 * q],     ww, hh.u.x);
                fma2(acc[2 * q + 1], ww, hh.u.y);
            }
        }
        float bias = fcb[n];
#pragma unroll
        for (int p = 0; p < 32; p++) {
            unsigned long long v = acc[p];
            add2(v, __shfl_xor_sync(0xffffffffu, v, 16));
            add2(v, __shfl_xor_sync(0xffffffffu, v, 8));
            add2(v, __shfl_xor_sync(0xffffffffu, v, 4));
            add2(v, __shfl_xor_sync(0xffffffffu, v, 2));
            add2(v, __shfl_xor_sync(0xffffffffu, v, 1));
            if (lane == 0) {
                U2 u; u.u = v;
                out[(size_t)(2 * p) * NCLS + n]     = u.f.x + bias;
                out[(size_t)(2 * p + 1) * NCLS + n] = u.f.y + bias;
            }
        }
    }
}

// ============================================================================
extern "C" void kernel_launch(void* const* d_in, const int* in_sizes, int n_in,
                              void* d_out, int out_size)
{
    const int*   x   = (const int*)d_in[0];
    const float* emb = (const float*)d_in[1];
    const float* W   = (const float*)d_in[2];
    const float* Wb  = (const float*)d_in[3];
    const float* fcw = (const float*)d_in[4];
    const float* fcb = (const float*)d_in[5];
    float* out = (float*)d_out;

    static const size_t lstm_smem = (size_t)64 * HID * 4 + (size_t)4096 * 16;
    static const size_t fc_smem   = (size_t)HID * 68 * 4;
    cudaFuncSetAttribute(lstm_kernel, cudaFuncAttributeMaxDynamicSharedMemorySize,
                         (int)lstm_smem);
    cudaFuncSetAttribute(fc_kernel, cudaFuncAttributeMaxDynamicSharedMemorySize,
                         (int)fc_smem);

    dim3 g1(SEQ * BATCH / 128, NG / 128);
    gx_kernel<<<g1, 256>>>(x, emb, W, Wb);

    lstm_kernel<<<NCTA, 512, lstm_smem>>>(W);

    fc_kernel<<<148, 256, fc_smem>>>(fcw, fcb, out);
}